// round 7
// baseline (speedup 1.0000x reference)
#include <cuda_runtime.h>

#define NN 50000
#define EE 800000
#define F 64
#define GG 64
#define CC 10
#define NBLK 49   // ceil(NN/1024)

typedef unsigned long long ull;

// ---------------- scratch (device globals; no allocation allowed) ----------------
// zero-region: [wdeg: NN floats][degcnt: NN ints][scan state: NBLK ull]
#define WDEG_OFF   0
#define DEGCNT_OFF (NN * 4)
#define STATE_OFF  (2 * NN * 4)
#define ZERO_BYTES (STATE_OFF + 64 * 8)
__device__ __align__(16) unsigned char g_zero[ZERO_BYTES];

__device__ __align__(16) float g_dinv[NN];
__device__ __align__(16) int   g_rowptr[NN + 1];
__device__ __align__(16) int   g_fill[NN];
__device__ __align__(16) int2  g_edges[EE];      // (col, bitcast(norm)) sorted by row
__device__ __align__(16) float g_T1[NN * F];
__device__ __align__(16) float g_T2[NN * F];     // holds U = S*T1
__device__ __align__(16) float g_H0[NN * F];
__device__ __align__(16) float g_H1[NN * F];
__device__ __align__(16) float g_pool[GG * F];

// ---------------- packed f32x2 helpers ----------------
__device__ __forceinline__ void fma2(ull& d, ull a, ull b) {
    asm("fma.rn.f32x2 %0, %1, %2, %0;" : "+l"(d) : "l"(a), "l"(b));
}
__device__ __forceinline__ ull pk2(float lo, float hi) {
    ull r;
    asm("mov.b64 %0, {%1, %2};" : "=l"(r) : "f"(lo), "f"(hi));
    return r;
}
__device__ __forceinline__ float2 unpk2(ull v) {
    float2 r;
    asm("mov.b64 {%0, %1}, %2;" : "=f"(r.x), "=f"(r.y) : "l"(v));
    return r;
}

// ---------------- build ----------------
__global__ void deg_kernel(const int* __restrict__ ei, const float* __restrict__ attr) {
    float* wdeg = (float*)(g_zero + WDEG_OFF);
    int* degcnt = (int*)(g_zero + DEGCNT_OFF);
    int e = blockIdx.x * blockDim.x + threadIdx.x;
    if (e < EE) {
        int r = ei[e];
        atomicAdd(&wdeg[r], attr[e]);
        atomicAdd(&degcnt[r], 1);
    }
}

// Single-kernel scan + dinv + rowptr/fill init. 49 blocks x 1024 (one wave).
__global__ void scan_kernel() {
    float* wdeg = (float*)(g_zero + WDEG_OFF);
    int* degcnt = (int*)(g_zero + DEGCNT_OFF);
    volatile ull* state = (volatile ull*)(g_zero + STATE_OFF);

    int tid = threadIdx.x;
    int b = blockIdx.x;
    int i = b * 1024 + tid;
    int v = (i < NN) ? degcnt[i] : 0;

    if (i < NN) {
        float d = wdeg[i];
        g_dinv[i] = (d > 0.f) ? rsqrtf(d) : 0.f;
    }

    int lane = tid & 31, wid = tid >> 5;
    int x = v;
    #pragma unroll
    for (int o = 1; o < 32; o <<= 1) {
        int y = __shfl_up_sync(0xFFFFFFFFu, x, o);
        if (lane >= o) x += y;
    }
    __shared__ int ws[32];
    __shared__ int s_prefix;
    if (lane == 31) ws[wid] = x;
    __syncthreads();
    if (wid == 0) {
        int s = ws[lane];
        #pragma unroll
        for (int o = 1; o < 32; o <<= 1) {
            int y = __shfl_up_sync(0xFFFFFFFFu, s, o);
            if (lane >= o) s += y;
        }
        ws[lane] = s;
    }
    __syncthreads();
    int blocksum = ws[31];

    if (tid == 0) {
        atomicExch((ull*)&state[b], (1ull << 32) | (unsigned)blocksum);
    }
    if (tid < 32) {
        int acc = 0;
        for (int p = tid; p < b; p += 32) {
            ull sv;
            do { sv = state[p]; } while ((sv >> 32) == 0);
            acc += (int)(unsigned)sv;
        }
        #pragma unroll
        for (int o = 16; o > 0; o >>= 1) acc += __shfl_down_sync(0xFFFFFFFFu, acc, o);
        if (tid == 0) s_prefix = acc;
    }
    __syncthreads();

    int excl = x - v + (wid > 0 ? ws[wid - 1] : 0);
    if (i < NN) {
        int r = excl + s_prefix;
        g_rowptr[i] = r;
        g_fill[i]   = r;
    }
    if (b == 0 && tid == 0) g_rowptr[NN] = EE;
}

__global__ void fill_kernel(const int* __restrict__ ei, const float* __restrict__ attr) {
    int e = blockIdx.x * blockDim.x + threadIdx.x;
    if (e < EE) {
        int r = ei[e];
        int c = ei[EE + e];
        float w = -attr[e] * g_dinv[r] * g_dinv[c];
        int pos = atomicAdd(&g_fill[r], 1);
        g_edges[pos] = make_int2(c, __float_as_int(w));
    }
}

// ---------------- sparse propagation: FULL warp per row, 2 edges/instr ----------------
// lane = 16*h + l. Half h processes edges s+h, s+h+2, ... ; lane l covers floats [4l,4l+4).
// Same row for all lanes -> uniform loop bounds -> no divergence. out = S * in.
__global__ void prop_kernel(const float* __restrict__ in, float* __restrict__ out) {
    int row = blockIdx.x * (blockDim.x >> 5) + (threadIdx.x >> 5);
    if (row >= NN) return;
    int lane = threadIdx.x & 31;
    int h = lane >> 4;
    int l = lane & 15;
    int s = g_rowptr[row], e = g_rowptr[row + 1];
    const float4* in4 = (const float4*)in;

    float4 A = make_float4(0.f, 0.f, 0.f, 0.f);
    float4 B = make_float4(0.f, 0.f, 0.f, 0.f);
    float4 Cq = make_float4(0.f, 0.f, 0.f, 0.f);
    float4 D = make_float4(0.f, 0.f, 0.f, 0.f);

    int j = s + h;
    // main: 8 edges per warp-iteration (4 per half), 4 gathers in flight per lane
    for (; j + 6 < e; j += 8) {
        int2 e0 = g_edges[j];
        int2 e1 = g_edges[j + 2];
        int2 e2 = g_edges[j + 4];
        int2 e3 = g_edges[j + 6];
        float4 v0 = in4[e0.x * 16 + l];
        float4 v1 = in4[e1.x * 16 + l];
        float4 v2 = in4[e2.x * 16 + l];
        float4 v3 = in4[e3.x * 16 + l];
        float w0 = __int_as_float(e0.y);
        float w1 = __int_as_float(e1.y);
        float w2 = __int_as_float(e2.y);
        float w3 = __int_as_float(e3.y);
        A.x = fmaf(w0, v0.x, A.x); A.y = fmaf(w0, v0.y, A.y);
        A.z = fmaf(w0, v0.z, A.z); A.w = fmaf(w0, v0.w, A.w);
        B.x = fmaf(w1, v1.x, B.x); B.y = fmaf(w1, v1.y, B.y);
        B.z = fmaf(w1, v1.z, B.z); B.w = fmaf(w1, v1.w, B.w);
        Cq.x = fmaf(w2, v2.x, Cq.x); Cq.y = fmaf(w2, v2.y, Cq.y);
        Cq.z = fmaf(w2, v2.z, Cq.z); Cq.w = fmaf(w2, v2.w, Cq.w);
        D.x = fmaf(w3, v3.x, D.x); D.y = fmaf(w3, v3.y, D.y);
        D.z = fmaf(w3, v3.z, D.z); D.w = fmaf(w3, v3.w, D.w);
    }
    // tail: step 2 per half (at most 1 extra iteration of divergence)
    for (; j < e; j += 2) {
        int2 ed = g_edges[j];
        float4 v = in4[ed.x * 16 + l];
        float w = __int_as_float(ed.y);
        A.x = fmaf(w, v.x, A.x); A.y = fmaf(w, v.y, A.y);
        A.z = fmaf(w, v.z, A.z); A.w = fmaf(w, v.w, A.w);
    }
    float4 r;
    r.x = (A.x + B.x) + (Cq.x + D.x);
    r.y = (A.y + B.y) + (Cq.y + D.y);
    r.z = (A.z + B.z) + (Cq.z + D.z);
    r.w = (A.w + B.w) + (Cq.w + D.w);

    // combine the two halves
    r.x += __shfl_xor_sync(0xFFFFFFFFu, r.x, 16);
    r.y += __shfl_xor_sync(0xFFFFFFFFu, r.y, 16);
    r.z += __shfl_xor_sync(0xFFFFFFFFu, r.z, 16);
    r.w += __shfl_xor_sync(0xFFFFFFFFu, r.w, 16);

    if (h == 0) ((float4*)out)[row * 16 + l] = r;
}

// ---------------- fused 3-matrix GEMM with packed f32x2 FMA ----------------
// out = relu?(x0@(W[0]-W[2]) + x1@W[1] + u@(2*W[2]) + b)   [algebraic T2 elimination]
// block: 64 rows x 64 cols, 256 threads, thread tile 4x4
template <bool RELU>
__global__ __launch_bounds__(256, 2) void gemm3_kernel(
    const float* __restrict__ x0, const float* __restrict__ x1, const float* __restrict__ x2,
    const float* __restrict__ W, const float* __restrict__ b, float* __restrict__ out) {
    extern __shared__ float smem[];
    float* sW = smem;             // 3*64*64
    float* sX = smem + 12288;     // 3*64*64
    int tid = threadIdx.x;
    int row0 = blockIdx.x * 64;

    // stage W with folding: slot0 = W0 - W2, slot1 = W1, slot2 = 2*W2
    {
        float4* d = (float4*)sW;
        const float4* g = (const float4*)W;
        #pragma unroll
        for (int i = tid; i < 1024; i += 256) {
            float4 w0 = g[i];
            float4 w2 = g[2048 + i];
            float4 f0, f2;
            f0.x = w0.x - w2.x; f0.y = w0.y - w2.y; f0.z = w0.z - w2.z; f0.w = w0.w - w2.w;
            f2.x = 2.f * w2.x; f2.y = 2.f * w2.y; f2.z = 2.f * w2.z; f2.w = 2.f * w2.w;
            d[i] = f0;
            d[1024 + i] = g[1024 + i];
            d[2048 + i] = f2;
        }
    }
    // stage X rows
    {
        for (int m = 0; m < 3; m++) {
            const float* src = (m == 0) ? x0 : (m == 1) ? x1 : x2;
            float4* d = (float4*)(sX + m * 4096);
            const float4* g = (const float4*)src;
            for (int i = tid; i < 1024; i += 256) {
                int r = i >> 4, c = i & 15;
                int row = row0 + r;
                d[i] = (row < NN) ? g[row * 16 + c] : make_float4(0.f, 0.f, 0.f, 0.f);
            }
        }
    }
    __syncthreads();

    int tc = tid & 15;
    int tr = tid >> 4;

    ull accA[4], accB[4];
    #pragma unroll
    for (int i = 0; i < 4; i++) { accA[i] = 0ull; accB[i] = 0ull; }

    const ull* wp = (const ull*)sW;
    const float* X0 = sX;
    const float* X1 = sX + 4096;
    const float* X2 = sX + 8192;

    #pragma unroll 4
    for (int k = 0; k < 64; k += 4) {
        float4 a0[4], a1[4], a2[4];
        #pragma unroll
        for (int i = 0; i < 4; i++) {
            int r = tr * 4 + i;
            a0[i] = *(const float4*)(X0 + r * 64 + k);
            a1[i] = *(const float4*)(X1 + r * 64 + k);
            a2[i] = *(const float4*)(X2 + r * 64 + k);
        }
        #pragma unroll
        for (int j = 0; j < 4; j++) {
            int wi = (k + j) * 32 + tc * 2;
            ull w0xy = wp[wi],        w0zw = wp[wi + 1];
            ull w1xy = wp[2048 + wi], w1zw = wp[2048 + wi + 1];
            ull w2xy = wp[4096 + wi], w2zw = wp[4096 + wi + 1];
            #pragma unroll
            for (int i = 0; i < 4; i++) {
                float p = ((const float*)&a0[i])[j];
                float q = ((const float*)&a1[i])[j];
                float t = ((const float*)&a2[i])[j];
                ull pp = pk2(p, p);
                ull qq = pk2(q, q);
                ull tt = pk2(t, t);
                fma2(accA[i], w0xy, pp);
                fma2(accB[i], w0zw, pp);
                fma2(accA[i], w1xy, qq);
                fma2(accB[i], w1zw, qq);
                fma2(accA[i], w2xy, tt);
                fma2(accB[i], w2zw, tt);
            }
        }
    }

    float4 bias = ((const float4*)b)[tc];
    #pragma unroll
    for (int i = 0; i < 4; i++) {
        int row = row0 + tr * 4 + i;
        if (row < NN) {
            float2 lo = unpk2(accA[i]);
            float2 hi = unpk2(accB[i]);
            float4 o;
            o.x = lo.x + bias.x;
            o.y = lo.y + bias.y;
            o.z = hi.x + bias.z;
            o.w = hi.y + bias.w;
            if (RELU) {
                o.x = fmaxf(o.x, 0.f); o.y = fmaxf(o.y, 0.f);
                o.z = fmaxf(o.z, 0.f); o.w = fmaxf(o.w, 0.f);
            }
            ((float4*)out)[row * 16 + tc] = o;
        }
    }
}

// ---------------- mean pool per graph (batch is sorted) ----------------
__device__ __forceinline__ int lower_bound_batch(const int* b, int val) {
    int lo = 0, hi = NN;
    while (lo < hi) {
        int mid = (lo + hi) >> 1;
        if (b[mid] < val) lo = mid + 1; else hi = mid;
    }
    return lo;
}

__global__ void pool_kernel(const float* __restrict__ h, const int* __restrict__ batch) {
    int g = blockIdx.x;
    __shared__ int s_lo, s_hi;
    if (threadIdx.x == 0) {
        s_lo = lower_bound_batch(batch, g);
        s_hi = lower_bound_batch(batch, g + 1);
    }
    __syncthreads();
    int lo = s_lo, hi = s_hi;
    int f = threadIdx.x & 63;
    int part = threadIdx.x >> 6;
    float acc = 0.f;
    for (int i = lo + part; i < hi; i += 4) acc += h[i * 64 + f];
    __shared__ float sh[4][64];
    sh[part][f] = acc;
    __syncthreads();
    if (part == 0) {
        float s = sh[0][f] + sh[1][f] + sh[2][f] + sh[3][f];
        float cnt = (float)(hi - lo);
        g_pool[g * 64 + f] = s / fmaxf(cnt, 1.f);
    }
}

// ---------------- final MLP ----------------
__global__ void mlp_kernel(const float* __restrict__ Wl1, const float* __restrict__ bl1,
                           const float* __restrict__ Wl2, const float* __restrict__ bl2,
                           float* __restrict__ out) {
    __shared__ float sp[GG * 64];
    __shared__ float sh1[GG * 32];
    int tid = threadIdx.x;
    for (int i = tid; i < GG * 64; i += 256) sp[i] = g_pool[i];
    __syncthreads();
    for (int i = tid; i < GG * 32; i += 256) {
        int g = i >> 5, c = i & 31;
        float s = bl1[c];
        #pragma unroll 8
        for (int k = 0; k < 64; k++) s += sp[g * 64 + k] * Wl1[k * 32 + c];
        sh1[i] = fmaxf(s, 0.f);
    }
    __syncthreads();
    for (int i = tid; i < GG * CC; i += 256) {
        int g = i / CC, c = i % CC;
        float s = bl2[c];
        #pragma unroll
        for (int k = 0; k < 32; k++) s += sh1[g * 32 + k] * Wl2[k * CC + c];
        out[i] = s;
    }
}

// ---------------- launcher ----------------
extern "C" void kernel_launch(void* const* d_in, const int* in_sizes, int n_in,
                              void* d_out, int out_size) {
    const float* x    = (const float*)d_in[0];
    const int*   ei   = (const int*)d_in[1];
    const float* attr = (const float*)d_in[2];
    const int*   bat  = (const int*)d_in[3];
    const float* W1 = (const float*)d_in[4];
    const float* b1 = (const float*)d_in[5];
    const float* W2 = (const float*)d_in[6];
    const float* b2 = (const float*)d_in[7];
    const float* W3 = (const float*)d_in[8];
    const float* b3 = (const float*)d_in[9];
    const float* Wl1 = (const float*)d_in[10];
    const float* bl1 = (const float*)d_in[11];
    const float* Wl2 = (const float*)d_in[12];
    const float* bl2 = (const float*)d_in[13];
    float* out = (float*)d_out;

    float *T1, *T2, *H0, *H1;
    void* zp;
    cudaGetSymbolAddress((void**)&T1, g_T1);
    cudaGetSymbolAddress((void**)&T2, g_T2);
    cudaGetSymbolAddress((void**)&H0, g_H0);
    cudaGetSymbolAddress((void**)&H1, g_H1);
    cudaGetSymbolAddress(&zp, g_zero);

    const int SMEM = (12288 + 12288) * (int)sizeof(float);  // 98304
    cudaFuncSetAttribute(gemm3_kernel<true>,  cudaFuncAttributeMaxDynamicSharedMemorySize, SMEM);
    cudaFuncSetAttribute(gemm3_kernel<false>, cudaFuncAttributeMaxDynamicSharedMemorySize, SMEM);

    const int NB_E = (EE + 255) / 256;
    const int NB_P = (NN + 7) / 8;        // warp per row, 8 warps/block
    const int NB_G = (NN + 63) / 64;

    cudaMemsetAsync(zp, 0, ZERO_BYTES);
    deg_kernel<<<NB_E, 256>>>(ei, attr);
    scan_kernel<<<NBLK, 1024>>>();
    fill_kernel<<<NB_E, 256>>>(ei, attr);

    // Layer 1: T1 = S*x, U = S*T1, out = x@(W0-W2) + T1@W1 + U@(2W2)
    prop_kernel<<<NB_P, 256>>>(x, T1);
    prop_kernel<<<NB_P, 256>>>(T1, T2);
    gemm3_kernel<true><<<NB_G, 256, SMEM>>>(x, T1, T2, W1, b1, H0);
    // Layer 2
    prop_kernel<<<NB_P, 256>>>(H0, T1);
    prop_kernel<<<NB_P, 256>>>(T1, T2);
    gemm3_kernel<true><<<NB_G, 256, SMEM>>>(H0, T1, T2, W2, b2, H1);
    // Layer 3
    prop_kernel<<<NB_P, 256>>>(H1, T1);
    prop_kernel<<<NB_P, 256>>>(T1, T2);
    gemm3_kernel<false><<<NB_G, 256, SMEM>>>(H1, T1, T2, W3, b3, H0);

    pool_kernel<<<GG, 256>>>(H0, bat);
    mlp_kernel<<<1, 256>>>(Wl1, bl1, Wl2, bl2, out);
}

// round 8
// speedup vs baseline: 1.0677x; 1.0677x over previous
#include <cuda_runtime.h>
#include <cuda_fp16.h>

#define NN 50000
#define EE 800000
#define F 64
#define GG 64
#define CC 10
#define NBLK 49   // ceil(NN/1024)

typedef unsigned long long ull;

// ---------------- scratch (device globals; no allocation allowed) ----------------
// zero-region: [wdeg: NN floats][degcnt: NN ints][scan state: NBLK ull]
#define WDEG_OFF   0
#define DEGCNT_OFF (NN * 4)
#define STATE_OFF  (2 * NN * 4)
#define ZERO_BYTES (STATE_OFF + 64 * 8)
__device__ __align__(16) unsigned char g_zero[ZERO_BYTES];

__device__ __align__(16) float  g_dinv[NN];
__device__ __align__(16) int    g_rowptr[NN + 1];
__device__ __align__(16) int    g_fill[NN];
__device__ __align__(16) int2   g_edges[EE];     // (col, bitcast(norm)) sorted by row
__device__ __align__(16) __half g_xh[NN * F];    // fp16 copy of x
__device__ __align__(16) __half g_T1[NN * F];    // fp16 T1 = S*in
__device__ __align__(16) __half g_T2[NN * F];    // fp16 U  = S*T1
__device__ __align__(16) __half g_H0[NN * F];    // fp16 layer outputs
__device__ __align__(16) __half g_H1[NN * F];
__device__ __align__(16) float  g_Hf[NN * F];    // fp32 final layer output (pooled)
__device__ __align__(16) float  g_pool[GG * F];

// ---------------- packed f32x2 helpers ----------------
__device__ __forceinline__ void fma2(ull& d, ull a, ull b) {
    asm("fma.rn.f32x2 %0, %1, %2, %0;" : "+l"(d) : "l"(a), "l"(b));
}
__device__ __forceinline__ ull pk2(float lo, float hi) {
    ull r;
    asm("mov.b64 %0, {%1, %2};" : "=l"(r) : "f"(lo), "f"(hi));
    return r;
}
__device__ __forceinline__ float2 unpk2(ull v) {
    float2 r;
    asm("mov.b64 {%0, %1}, %2;" : "=f"(r.x), "=f"(r.y) : "l"(v));
    return r;
}

// fp16 pack/unpack helpers (8 bytes = 4 features)
__device__ __forceinline__ float4 h4_to_f4(uint2 u) {
    float2 a = __half22float2(*reinterpret_cast<const __half2*>(&u.x));
    float2 b = __half22float2(*reinterpret_cast<const __half2*>(&u.y));
    return make_float4(a.x, a.y, b.x, b.y);
}
__device__ __forceinline__ uint2 f4_to_h4(float4 v) {
    __half2 a = __floats2half2_rn(v.x, v.y);
    __half2 b = __floats2half2_rn(v.z, v.w);
    uint2 u;
    u.x = *reinterpret_cast<unsigned*>(&a);
    u.y = *reinterpret_cast<unsigned*>(&b);
    return u;
}

// ---------------- build ----------------
__global__ void deg_kernel(const int* __restrict__ ei, const float* __restrict__ attr) {
    float* wdeg = (float*)(g_zero + WDEG_OFF);
    int* degcnt = (int*)(g_zero + DEGCNT_OFF);
    int e = blockIdx.x * blockDim.x + threadIdx.x;
    if (e < EE) {
        int r = ei[e];
        atomicAdd(&wdeg[r], attr[e]);
        atomicAdd(&degcnt[r], 1);
    }
}

// Single-kernel scan + dinv + rowptr/fill init. 49 blocks x 1024 (one wave).
__global__ void scan_kernel() {
    float* wdeg = (float*)(g_zero + WDEG_OFF);
    int* degcnt = (int*)(g_zero + DEGCNT_OFF);
    volatile ull* state = (volatile ull*)(g_zero + STATE_OFF);

    int tid = threadIdx.x;
    int b = blockIdx.x;
    int i = b * 1024 + tid;
    int v = (i < NN) ? degcnt[i] : 0;

    if (i < NN) {
        float d = wdeg[i];
        g_dinv[i] = (d > 0.f) ? rsqrtf(d) : 0.f;
    }

    int lane = tid & 31, wid = tid >> 5;
    int x = v;
    #pragma unroll
    for (int o = 1; o < 32; o <<= 1) {
        int y = __shfl_up_sync(0xFFFFFFFFu, x, o);
        if (lane >= o) x += y;
    }
    __shared__ int ws[32];
    __shared__ int s_prefix;
    if (lane == 31) ws[wid] = x;
    __syncthreads();
    if (wid == 0) {
        int s = ws[lane];
        #pragma unroll
        for (int o = 1; o < 32; o <<= 1) {
            int y = __shfl_up_sync(0xFFFFFFFFu, s, o);
            if (lane >= o) s += y;
        }
        ws[lane] = s;
    }
    __syncthreads();
    int blocksum = ws[31];

    if (tid == 0) {
        atomicExch((ull*)&state[b], (1ull << 32) | (unsigned)blocksum);
    }
    if (tid < 32) {
        int acc = 0;
        for (int p = tid; p < b; p += 32) {
            ull sv;
            do { sv = state[p]; } while ((sv >> 32) == 0);
            acc += (int)(unsigned)sv;
        }
        #pragma unroll
        for (int o = 16; o > 0; o >>= 1) acc += __shfl_down_sync(0xFFFFFFFFu, acc, o);
        if (tid == 0) s_prefix = acc;
    }
    __syncthreads();

    int excl = x - v + (wid > 0 ? ws[wid - 1] : 0);
    if (i < NN) {
        int r = excl + s_prefix;
        g_rowptr[i] = r;
        g_fill[i]   = r;
    }
    if (b == 0 && tid == 0) g_rowptr[NN] = EE;
}

__global__ void fill_kernel(const int* __restrict__ ei, const float* __restrict__ attr) {
    int e = blockIdx.x * blockDim.x + threadIdx.x;
    if (e < EE) {
        int r = ei[e];
        int c = ei[EE + e];
        float w = -attr[e] * g_dinv[r] * g_dinv[c];
        int pos = atomicAdd(&g_fill[r], 1);
        g_edges[pos] = make_int2(c, __float_as_int(w));
    }
}

// ---------------- x -> fp16 copy ----------------
__global__ void cvt_kernel(const float4* __restrict__ in) {
    int i = blockIdx.x * blockDim.x + threadIdx.x;
    if (i < NN * 16) {
        ((uint2*)g_xh)[i] = f4_to_h4(in[i]);
    }
}

// ---------------- sparse propagation: half-warp (16 lanes) per row, fp16 features ----
// 16 lanes x 8B (4 halves) = 128B = one row. out = S * in. fp32 accumulate.
__global__ void prop_kernel(const uint2* __restrict__ in, uint2* __restrict__ out) {
    int idx = blockIdx.x * blockDim.x + threadIdx.x;
    int row = idx >> 4;
    if (row >= NN) return;
    int l = idx & 15;
    int s = g_rowptr[row], e = g_rowptr[row + 1];

    float4 A = make_float4(0.f, 0.f, 0.f, 0.f);
    float4 B = make_float4(0.f, 0.f, 0.f, 0.f);
    float4 Cq = make_float4(0.f, 0.f, 0.f, 0.f);
    float4 D = make_float4(0.f, 0.f, 0.f, 0.f);
    int j = s;
    for (; j + 4 <= e; j += 4) {
        int2 e0 = g_edges[j];
        int2 e1 = g_edges[j + 1];
        int2 e2 = g_edges[j + 2];
        int2 e3 = g_edges[j + 3];
        uint2 u0 = in[e0.x * 16 + l];
        uint2 u1 = in[e1.x * 16 + l];
        uint2 u2 = in[e2.x * 16 + l];
        uint2 u3 = in[e3.x * 16 + l];
        float w0 = __int_as_float(e0.y);
        float w1 = __int_as_float(e1.y);
        float w2 = __int_as_float(e2.y);
        float w3 = __int_as_float(e3.y);
        float4 v0 = h4_to_f4(u0);
        float4 v1 = h4_to_f4(u1);
        float4 v2 = h4_to_f4(u2);
        float4 v3 = h4_to_f4(u3);
        A.x = fmaf(w0, v0.x, A.x); A.y = fmaf(w0, v0.y, A.y);
        A.z = fmaf(w0, v0.z, A.z); A.w = fmaf(w0, v0.w, A.w);
        B.x = fmaf(w1, v1.x, B.x); B.y = fmaf(w1, v1.y, B.y);
        B.z = fmaf(w1, v1.z, B.z); B.w = fmaf(w1, v1.w, B.w);
        Cq.x = fmaf(w2, v2.x, Cq.x); Cq.y = fmaf(w2, v2.y, Cq.y);
        Cq.z = fmaf(w2, v2.z, Cq.z); Cq.w = fmaf(w2, v2.w, Cq.w);
        D.x = fmaf(w3, v3.x, D.x); D.y = fmaf(w3, v3.y, D.y);
        D.z = fmaf(w3, v3.z, D.z); D.w = fmaf(w3, v3.w, D.w);
    }
    for (; j < e; j++) {
        int2 ed = g_edges[j];
        uint2 u = in[ed.x * 16 + l];
        float w = __int_as_float(ed.y);
        float4 v = h4_to_f4(u);
        A.x = fmaf(w, v.x, A.x); A.y = fmaf(w, v.y, A.y);
        A.z = fmaf(w, v.z, A.z); A.w = fmaf(w, v.w, A.w);
    }
    float4 r;
    r.x = (A.x + B.x) + (Cq.x + D.x);
    r.y = (A.y + B.y) + (Cq.y + D.y);
    r.z = (A.z + B.z) + (Cq.z + D.z);
    r.w = (A.w + B.w) + (Cq.w + D.w);
    out[row * 16 + l] = f4_to_h4(r);
}

// ---------------- fused 3-matrix GEMM with packed f32x2 FMA ----------------
// out = relu?(x0@(W[0]-W[2]) + x1@W[1] + u@(2*W[2]) + b)   [algebraic T2 elimination]
// inputs fp16, smem/compute fp32, output fp16 (OUTH) or fp32.
// block: 64 rows x 64 cols, 256 threads, thread tile 4x4
template <bool RELU, bool OUTH>
__global__ __launch_bounds__(256, 2) void gemm3_kernel(
    const uint2* __restrict__ x0, const uint2* __restrict__ x1, const uint2* __restrict__ x2,
    const float* __restrict__ W, const float* __restrict__ b, void* __restrict__ out) {
    extern __shared__ float smem[];
    float* sW = smem;             // 3*64*64
    float* sX = smem + 12288;     // 3*64*64
    int tid = threadIdx.x;
    int row0 = blockIdx.x * 64;

    // stage W with folding: slot0 = W0 - W2, slot1 = W1, slot2 = 2*W2
    {
        float4* d = (float4*)sW;
        const float4* g = (const float4*)W;
        #pragma unroll
        for (int i = tid; i < 1024; i += 256) {
            float4 w0 = g[i];
            float4 w2 = g[2048 + i];
            float4 f0, f2;
            f0.x = w0.x - w2.x; f0.y = w0.y - w2.y; f0.z = w0.z - w2.z; f0.w = w0.w - w2.w;
            f2.x = 2.f * w2.x; f2.y = 2.f * w2.y; f2.z = 2.f * w2.z; f2.w = 2.f * w2.w;
            d[i] = f0;
            d[1024 + i] = g[1024 + i];
            d[2048 + i] = f2;
        }
    }
    // stage X rows (fp16 -> fp32)
    {
        for (int m = 0; m < 3; m++) {
            const uint2* src = (m == 0) ? x0 : (m == 1) ? x1 : x2;
            float4* d = (float4*)(sX + m * 4096);
            for (int i = tid; i < 1024; i += 256) {
                int r = i >> 4, c = i & 15;
                int row = row0 + r;
                if (row < NN) {
                    d[i] = h4_to_f4(src[row * 16 + c]);
                } else {
                    d[i] = make_float4(0.f, 0.f, 0.f, 0.f);
                }
            }
        }
    }
    __syncthreads();

    int tc = tid & 15;
    int tr = tid >> 4;

    ull accA[4], accB[4];
    #pragma unroll
    for (int i = 0; i < 4; i++) { accA[i] = 0ull; accB[i] = 0ull; }

    const ull* wp = (const ull*)sW;
    const float* X0 = sX;
    const float* X1 = sX + 4096;
    const float* X2 = sX + 8192;

    #pragma unroll 4
    for (int k = 0; k < 64; k += 4) {
        float4 a0[4], a1[4], a2[4];
        #pragma unroll
        for (int i = 0; i < 4; i++) {
            int r = tr * 4 + i;
            a0[i] = *(const float4*)(X0 + r * 64 + k);
            a1[i] = *(const float4*)(X1 + r * 64 + k);
            a2[i] = *(const float4*)(X2 + r * 64 + k);
        }
        #pragma unroll
        for (int j = 0; j < 4; j++) {
            int wi = (k + j) * 32 + tc * 2;
            ull w0xy = wp[wi],        w0zw = wp[wi + 1];
            ull w1xy = wp[2048 + wi], w1zw = wp[2048 + wi + 1];
            ull w2xy = wp[4096 + wi], w2zw = wp[4096 + wi + 1];
            #pragma unroll
            for (int i = 0; i < 4; i++) {
                float p = ((const float*)&a0[i])[j];
                float q = ((const float*)&a1[i])[j];
                float t = ((const float*)&a2[i])[j];
                ull pp = pk2(p, p);
                ull qq = pk2(q, q);
                ull tt = pk2(t, t);
                fma2(accA[i], w0xy, pp);
                fma2(accB[i], w0zw, pp);
                fma2(accA[i], w1xy, qq);
                fma2(accB[i], w1zw, qq);
                fma2(accA[i], w2xy, tt);
                fma2(accB[i], w2zw, tt);
            }
        }
    }

    float4 bias = ((const float4*)b)[tc];
    #pragma unroll
    for (int i = 0; i < 4; i++) {
        int row = row0 + tr * 4 + i;
        if (row < NN) {
            float2 lo = unpk2(accA[i]);
            float2 hi = unpk2(accB[i]);
            float4 o;
            o.x = lo.x + bias.x;
            o.y = lo.y + bias.y;
            o.z = hi.x + bias.z;
            o.w = hi.y + bias.w;
            if (RELU) {
                o.x = fmaxf(o.x, 0.f); o.y = fmaxf(o.y, 0.f);
                o.z = fmaxf(o.z, 0.f); o.w = fmaxf(o.w, 0.f);
            }
            if (OUTH) {
                ((uint2*)out)[row * 16 + tc] = f4_to_h4(o);
            } else {
                ((float4*)out)[row * 16 + tc] = o;
            }
        }
    }
}

// ---------------- mean pool per graph (batch is sorted) ----------------
__device__ __forceinline__ int lower_bound_batch(const int* b, int val) {
    int lo = 0, hi = NN;
    while (lo < hi) {
        int mid = (lo + hi) >> 1;
        if (b[mid] < val) lo = mid + 1; else hi = mid;
    }
    return lo;
}

__global__ void pool_kernel(const float* __restrict__ h, const int* __restrict__ batch) {
    int g = blockIdx.x;
    __shared__ int s_lo, s_hi;
    if (threadIdx.x == 0) {
        s_lo = lower_bound_batch(batch, g);
        s_hi = lower_bound_batch(batch, g + 1);
    }
    __syncthreads();
    int lo = s_lo, hi = s_hi;
    int f = threadIdx.x & 63;
    int part = threadIdx.x >> 6;
    float acc = 0.f;
    for (int i = lo + part; i < hi; i += 4) acc += h[i * 64 + f];
    __shared__ float sh[4][64];
    sh[part][f] = acc;
    __syncthreads();
    if (part == 0) {
        float s = sh[0][f] + sh[1][f] + sh[2][f] + sh[3][f];
        float cnt = (float)(hi - lo);
        g_pool[g * 64 + f] = s / fmaxf(cnt, 1.f);
    }
}

// ---------------- final MLP ----------------
__global__ void mlp_kernel(const float* __restrict__ Wl1, const float* __restrict__ bl1,
                           const float* __restrict__ Wl2, const float* __restrict__ bl2,
                           float* __restrict__ out) {
    __shared__ float sp[GG * 64];
    __shared__ float sh1[GG * 32];
    int tid = threadIdx.x;
    for (int i = tid; i < GG * 64; i += 256) sp[i] = g_pool[i];
    __syncthreads();
    for (int i = tid; i < GG * 32; i += 256) {
        int g = i >> 5, c = i & 31;
        float s = bl1[c];
        #pragma unroll 8
        for (int k = 0; k < 64; k++) s += sp[g * 64 + k] * Wl1[k * 32 + c];
        sh1[i] = fmaxf(s, 0.f);
    }
    __syncthreads();
    for (int i = tid; i < GG * CC; i += 256) {
        int g = i / CC, c = i % CC;
        float s = bl2[c];
        #pragma unroll
        for (int k = 0; k < 32; k++) s += sh1[g * 32 + k] * Wl2[k * CC + c];
        out[i] = s;
    }
}

// ---------------- launcher ----------------
extern "C" void kernel_launch(void* const* d_in, const int* in_sizes, int n_in,
                              void* d_out, int out_size) {
    const float* x    = (const float*)d_in[0];
    const int*   ei   = (const int*)d_in[1];
    const float* attr = (const float*)d_in[2];
    const int*   bat  = (const int*)d_in[3];
    const float* W1 = (const float*)d_in[4];
    const float* b1 = (const float*)d_in[5];
    const float* W2 = (const float*)d_in[6];
    const float* b2 = (const float*)d_in[7];
    const float* W3 = (const float*)d_in[8];
    const float* b3 = (const float*)d_in[9];
    const float* Wl1 = (const float*)d_in[10];
    const float* bl1 = (const float*)d_in[11];
    const float* Wl2 = (const float*)d_in[12];
    const float* bl2 = (const float*)d_in[13];
    float* out = (float*)d_out;

    uint2 *xh, *T1, *T2, *H0, *H1;
    float *Hf;
    void* zp;
    cudaGetSymbolAddress((void**)&xh, g_xh);
    cudaGetSymbolAddress((void**)&T1, g_T1);
    cudaGetSymbolAddress((void**)&T2, g_T2);
    cudaGetSymbolAddress((void**)&H0, g_H0);
    cudaGetSymbolAddress((void**)&H1, g_H1);
    cudaGetSymbolAddress((void**)&Hf, g_Hf);
    cudaGetSymbolAddress(&zp, g_zero);

    const int SMEM = (12288 + 12288) * (int)sizeof(float);  // 98304
    cudaFuncSetAttribute((const void*)gemm3_kernel<true, true>,
                         cudaFuncAttributeMaxDynamicSharedMemorySize, SMEM);
    cudaFuncSetAttribute((const void*)gemm3_kernel<false, false>,
                         cudaFuncAttributeMaxDynamicSharedMemorySize, SMEM);

    const int NB_E = (EE + 255) / 256;
    const int NB_P = (NN * 16 + 255) / 256;   // 16 threads per row
    const int NB_G = (NN + 63) / 64;
    const int NB_C = (NN * 16 + 255) / 256;

    cudaMemsetAsync(zp, 0, ZERO_BYTES);
    deg_kernel<<<NB_E, 256>>>(ei, attr);
    cvt_kernel<<<NB_C, 256>>>((const float4*)x);
    scan_kernel<<<NBLK, 1024>>>();
    fill_kernel<<<NB_E, 256>>>(ei, attr);

    // Layer 1: T1 = S*xh, U = S*T1, H0 = relu(xh@(W0-W2) + T1@W1 + U@2W2 + b)
    prop_kernel<<<NB_P, 256>>>(xh, T1);
    prop_kernel<<<NB_P, 256>>>(T1, T2);
    gemm3_kernel<true, true><<<NB_G, 256, SMEM>>>(xh, T1, T2, W1, b1, H0);
    // Layer 2
    prop_kernel<<<NB_P, 256>>>(H0, T1);
    prop_kernel<<<NB_P, 256>>>(T1, T2);
    gemm3_kernel<true, true><<<NB_G, 256, SMEM>>>(H0, T1, T2, W2, b2, H1);
    // Layer 3 (fp32 output for pooling)
    prop_kernel<<<NB_P, 256>>>(H1, T1);
    prop_kernel<<<NB_P, 256>>>(T1, T2);
    gemm3_kernel<false, false><<<NB_G, 256, SMEM>>>(H1, T1, T2, W3, b3, Hf);

    pool_kernel<<<GG, 256>>>(Hf, bat);
    mlp_kernel<<<1, 256>>>(Wl1, bl1, Wl2, bl2, out);
}

// round 9
// speedup vs baseline: 1.2084x; 1.1318x over previous
#include <cuda_runtime.h>
#include <cuda_fp16.h>
#include <mma.h>

using namespace nvcuda;

#define NN 50000
#define EE 800000
#define F 64
#define GG 64
#define CC 10
#define NBLK 49   // ceil(NN/1024)

typedef unsigned long long ull;

// ---------------- scratch (device globals; no allocation allowed) ----------------
#define WDEG_OFF   0
#define DEGCNT_OFF (NN * 4)
#define STATE_OFF  (2 * NN * 4)
#define ZERO_BYTES (STATE_OFF + 64 * 8)
__device__ __align__(16) unsigned char g_zero[ZERO_BYTES];

__device__ __align__(16) float  g_dinv[NN];
__device__ __align__(16) int    g_rowptr[NN + 1];
__device__ __align__(16) int    g_fill[NN];
__device__ __align__(16) int2   g_edges[EE];     // (col, bitcast(norm)) sorted by row
__device__ __align__(16) __half g_xh[NN * F];    // fp16 copy of x
__device__ __align__(16) __half g_T1[NN * F];
__device__ __align__(16) __half g_T2[NN * F];
__device__ __align__(16) __half g_H0[NN * F];
__device__ __align__(16) __half g_H1[NN * F];
__device__ __align__(16) float  g_Hf[NN * F];    // fp32 final layer output
__device__ __align__(16) float  g_pool[GG * F];

// fp16 pack/unpack helpers (8 bytes = 4 features)
__device__ __forceinline__ float4 h4_to_f4(uint2 u) {
    float2 a = __half22float2(*reinterpret_cast<const __half2*>(&u.x));
    float2 b = __half22float2(*reinterpret_cast<const __half2*>(&u.y));
    return make_float4(a.x, a.y, b.x, b.y);
}
__device__ __forceinline__ uint2 f4_to_h4(float4 v) {
    __half2 a = __floats2half2_rn(v.x, v.y);
    __half2 b = __floats2half2_rn(v.z, v.w);
    uint2 u;
    u.x = *reinterpret_cast<unsigned*>(&a);
    u.y = *reinterpret_cast<unsigned*>(&b);
    return u;
}

// ---------------- build: 4 edges/thread, vectorized streams ----------------
__global__ void deg_kernel(const int* __restrict__ ei, const float* __restrict__ attr) {
    float* wdeg = (float*)(g_zero + WDEG_OFF);
    int* degcnt = (int*)(g_zero + DEGCNT_OFF);
    int t = blockIdx.x * blockDim.x + threadIdx.x;
    int e0 = t * 4;
    if (e0 + 3 < EE) {
        int4 r4 = *(const int4*)(ei + e0);
        float4 a4 = *(const float4*)(attr + e0);
        atomicAdd(&wdeg[r4.x], a4.x); atomicAdd(&degcnt[r4.x], 1);
        atomicAdd(&wdeg[r4.y], a4.y); atomicAdd(&degcnt[r4.y], 1);
        atomicAdd(&wdeg[r4.z], a4.z); atomicAdd(&degcnt[r4.z], 1);
        atomicAdd(&wdeg[r4.w], a4.w); atomicAdd(&degcnt[r4.w], 1);
    } else {
        for (int e = e0; e < EE; e++) {
            int r = ei[e];
            atomicAdd(&wdeg[r], attr[e]);
            atomicAdd(&degcnt[r], 1);
        }
    }
}

// Single-kernel scan + dinv + rowptr/fill init. 49 blocks x 1024 (one wave).
__global__ void scan_kernel() {
    float* wdeg = (float*)(g_zero + WDEG_OFF);
    int* degcnt = (int*)(g_zero + DEGCNT_OFF);
    volatile ull* state = (volatile ull*)(g_zero + STATE_OFF);

    int tid = threadIdx.x;
    int b = blockIdx.x;
    int i = b * 1024 + tid;
    int v = (i < NN) ? degcnt[i] : 0;

    if (i < NN) {
        float d = wdeg[i];
        g_dinv[i] = (d > 0.f) ? rsqrtf(d) : 0.f;
    }

    int lane = tid & 31, wid = tid >> 5;
    int x = v;
    #pragma unroll
    for (int o = 1; o < 32; o <<= 1) {
        int y = __shfl_up_sync(0xFFFFFFFFu, x, o);
        if (lane >= o) x += y;
    }
    __shared__ int ws[32];
    __shared__ int s_prefix;
    if (lane == 31) ws[wid] = x;
    __syncthreads();
    if (wid == 0) {
        int s = ws[lane];
        #pragma unroll
        for (int o = 1; o < 32; o <<= 1) {
            int y = __shfl_up_sync(0xFFFFFFFFu, s, o);
            if (lane >= o) s += y;
        }
        ws[lane] = s;
    }
    __syncthreads();
    int blocksum = ws[31];

    if (tid == 0) {
        atomicExch((ull*)&state[b], (1ull << 32) | (unsigned)blocksum);
    }
    if (tid < 32) {
        int acc = 0;
        for (int p = tid; p < b; p += 32) {
            ull sv;
            do { sv = state[p]; } while ((sv >> 32) == 0);
            acc += (int)(unsigned)sv;
        }
        #pragma unroll
        for (int o = 16; o > 0; o >>= 1) acc += __shfl_down_sync(0xFFFFFFFFu, acc, o);
        if (tid == 0) s_prefix = acc;
    }
    __syncthreads();

    int excl = x - v + (wid > 0 ? ws[wid - 1] : 0);
    if (i < NN) {
        int r = excl + s_prefix;
        g_rowptr[i] = r;
        g_fill[i]   = r;
    }
    if (b == 0 && tid == 0) g_rowptr[NN] = EE;
}

__global__ void fill_kernel(const int* __restrict__ ei, const float* __restrict__ attr) {
    int t = blockIdx.x * blockDim.x + threadIdx.x;
    int e0 = t * 4;
    if (e0 + 3 < EE) {
        int4 r4 = *(const int4*)(ei + e0);
        int4 c4 = *(const int4*)(ei + EE + e0);
        float4 a4 = *(const float4*)(attr + e0);
        float w0 = -a4.x * g_dinv[r4.x] * g_dinv[c4.x];
        float w1 = -a4.y * g_dinv[r4.y] * g_dinv[c4.y];
        float w2 = -a4.z * g_dinv[r4.z] * g_dinv[c4.z];
        float w3 = -a4.w * g_dinv[r4.w] * g_dinv[c4.w];
        int p0 = atomicAdd(&g_fill[r4.x], 1);
        int p1 = atomicAdd(&g_fill[r4.y], 1);
        int p2 = atomicAdd(&g_fill[r4.z], 1);
        int p3 = atomicAdd(&g_fill[r4.w], 1);
        g_edges[p0] = make_int2(c4.x, __float_as_int(w0));
        g_edges[p1] = make_int2(c4.y, __float_as_int(w1));
        g_edges[p2] = make_int2(c4.z, __float_as_int(w2));
        g_edges[p3] = make_int2(c4.w, __float_as_int(w3));
    } else {
        for (int e = e0; e < EE; e++) {
            int r = ei[e];
            int c = ei[EE + e];
            float w = -attr[e] * g_dinv[r] * g_dinv[c];
            int pos = atomicAdd(&g_fill[r], 1);
            g_edges[pos] = make_int2(c, __float_as_int(w));
        }
    }
}

// ---------------- x -> fp16 copy ----------------
__global__ void cvt_kernel(const float4* __restrict__ in) {
    int i = blockIdx.x * blockDim.x + threadIdx.x;
    if (i < NN * 16) {
        ((uint2*)g_xh)[i] = f4_to_h4(in[i]);
    }
}

// ---------------- sparse propagation: half-warp (16 lanes) per row, fp16 features ----
__global__ void prop_kernel(const uint2* __restrict__ in, uint2* __restrict__ out) {
    int idx = blockIdx.x * blockDim.x + threadIdx.x;
    int row = idx >> 4;
    if (row >= NN) return;
    int l = idx & 15;
    int s = g_rowptr[row], e = g_rowptr[row + 1];

    float4 A = make_float4(0.f, 0.f, 0.f, 0.f);
    float4 B = make_float4(0.f, 0.f, 0.f, 0.f);
    float4 Cq = make_float4(0.f, 0.f, 0.f, 0.f);
    float4 D = make_float4(0.f, 0.f, 0.f, 0.f);
    int j = s;
    for (; j + 4 <= e; j += 4) {
        int2 e0 = g_edges[j];
        int2 e1 = g_edges[j + 1];
        int2 e2 = g_edges[j + 2];
        int2 e3 = g_edges[j + 3];
        uint2 u0 = in[e0.x * 16 + l];
        uint2 u1 = in[e1.x * 16 + l];
        uint2 u2 = in[e2.x * 16 + l];
        uint2 u3 = in[e3.x * 16 + l];
        float w0 = __int_as_float(e0.y);
        float w1 = __int_as_float(e1.y);
        float w2 = __int_as_float(e2.y);
        float w3 = __int_as_float(e3.y);
        float4 v0 = h4_to_f4(u0);
        float4 v1 = h4_to_f4(u1);
        float4 v2 = h4_to_f4(u2);
        float4 v3 = h4_to_f4(u3);
        A.x = fmaf(w0, v0.x, A.x); A.y = fmaf(w0, v0.y, A.y);
        A.z = fmaf(w0, v0.z, A.z); A.w = fmaf(w0, v0.w, A.w);
        B.x = fmaf(w1, v1.x, B.x); B.y = fmaf(w1, v1.y, B.y);
        B.z = fmaf(w1, v1.z, B.z); B.w = fmaf(w1, v1.w, B.w);
        Cq.x = fmaf(w2, v2.x, Cq.x); Cq.y = fmaf(w2, v2.y, Cq.y);
        Cq.z = fmaf(w2, v2.z, Cq.z); Cq.w = fmaf(w2, v2.w, Cq.w);
        D.x = fmaf(w3, v3.x, D.x); D.y = fmaf(w3, v3.y, D.y);
        D.z = fmaf(w3, v3.z, D.z); D.w = fmaf(w3, v3.w, D.w);
    }
    for (; j < e; j++) {
        int2 ed = g_edges[j];
        uint2 u = in[ed.x * 16 + l];
        float w = __int_as_float(ed.y);
        float4 v = h4_to_f4(u);
        A.x = fmaf(w, v.x, A.x); A.y = fmaf(w, v.y, A.y);
        A.z = fmaf(w, v.z, A.z); A.w = fmaf(w, v.w, A.w);
    }
    float4 r;
    r.x = (A.x + B.x) + (Cq.x + D.x);
    r.y = (A.y + B.y) + (Cq.y + D.y);
    r.z = (A.z + B.z) + (Cq.z + D.z);
    r.w = (A.w + B.w) + (Cq.w + D.w);
    out[row * 16 + l] = f4_to_h4(r);
}

// ---------------- tensor-core GEMM: out = relu?([x|T1|U] @ [W0-W2; W1; 2W2] + b) -----
// A: 64x192 fp16 (3 mats concatenated in K), B: 192x64 fp16 (folded weights, fp32->fp16)
// 8 warps, each owns 2 of the 16 m16n16 tiles; fp32 accumulate.
#define SA_STRIDE 208   // 192 + 16 padding, multiple of 16
template <bool RELU, bool OUTH>
__global__ __launch_bounds__(256, 2) void gemm3_kernel(
    const uint2* __restrict__ x0, const uint2* __restrict__ x1, const uint2* __restrict__ x2,
    const float* __restrict__ W, const float* __restrict__ b, void* __restrict__ out) {
    extern __shared__ char smem[];
    __half* sA = (__half*)smem;                          // 64 x SA_STRIDE fp16 = 26624 B
    __half* sB = (__half*)(smem + 64 * SA_STRIDE * 2);   // 192 x 64 fp16 = 24576 B
    float*  sC = (float*)smem;                           // reused after MMA: 64x64 fp32

    int tid = threadIdx.x;
    int row0 = blockIdx.x * 64;

    // stage A (fp16 passthrough)
    #pragma unroll
    for (int m = 0; m < 3; m++) {
        const uint2* src = (m == 0) ? x0 : (m == 1) ? x1 : x2;
        for (int i = tid; i < 1024; i += 256) {
            int r = i >> 4, c = i & 15;
            int row = row0 + r;
            uint2 v = (row < NN) ? src[row * 16 + c] : make_uint2(0u, 0u);
            *(uint2*)&sA[r * SA_STRIDE + m * 64 + c * 4] = v;
        }
    }
    // stage B with fold: rows [0:64)=W0-W2, [64:128)=W1, [128:192)=2*W2 (fp32 -> fp16)
    for (int i = tid; i < 1024; i += 256) {
        int k = i >> 4, c = i & 15;
        float4 w0 = ((const float4*)W)[i];
        float4 w1 = ((const float4*)W)[1024 + i];
        float4 w2 = ((const float4*)W)[2048 + i];
        float4 f0 = make_float4(w0.x - w2.x, w0.y - w2.y, w0.z - w2.z, w0.w - w2.w);
        float4 f2 = make_float4(2.f * w2.x, 2.f * w2.y, 2.f * w2.z, 2.f * w2.w);
        *(uint2*)&sB[k * 64 + c * 4]         = f4_to_h4(f0);
        *(uint2*)&sB[(64 + k) * 64 + c * 4]  = f4_to_h4(w1);
        *(uint2*)&sB[(128 + k) * 64 + c * 4] = f4_to_h4(f2);
    }
    __syncthreads();

    // MMA: warp w -> tiles (wm, wn) and (wm+2, wn)
    int w = tid >> 5;
    int wm = w >> 2;   // 0..1
    int wn = w & 3;    // 0..3
    wmma::fragment<wmma::accumulator, 16, 16, 16, float> acc0, acc1;
    wmma::fill_fragment(acc0, 0.f);
    wmma::fill_fragment(acc1, 0.f);
    #pragma unroll
    for (int k = 0; k < 192; k += 16) {
        wmma::fragment<wmma::matrix_a, 16, 16, 16, __half, wmma::row_major> a0, a1;
        wmma::fragment<wmma::matrix_b, 16, 16, 16, __half, wmma::row_major> bf;
        wmma::load_matrix_sync(a0, sA + (wm * 16) * SA_STRIDE + k, SA_STRIDE);
        wmma::load_matrix_sync(a1, sA + (wm * 16 + 32) * SA_STRIDE + k, SA_STRIDE);
        wmma::load_matrix_sync(bf, sB + k * 64 + wn * 16, 64);
        wmma::mma_sync(acc0, a0, bf, acc0);
        wmma::mma_sync(acc1, a1, bf, acc1);
    }
    __syncthreads();  // done reading sA; reuse as sC
    wmma::store_matrix_sync(sC + (wm * 16) * 64 + wn * 16, acc0, 64, wmma::mem_row_major);
    wmma::store_matrix_sync(sC + (wm * 16 + 32) * 64 + wn * 16, acc1, 64, wmma::mem_row_major);
    __syncthreads();

    // epilogue: bias + relu + store
    for (int i = tid; i < 1024; i += 256) {
        int r = i >> 4, c = i & 15;
        int row = row0 + r;
        if (row < NN) {
            float4 v = ((const float4*)sC)[i];
            float4 bias = ((const float4*)b)[c];
            v.x += bias.x; v.y += bias.y; v.z += bias.z; v.w += bias.w;
            if (RELU) {
                v.x = fmaxf(v.x, 0.f); v.y = fmaxf(v.y, 0.f);
                v.z = fmaxf(v.z, 0.f); v.w = fmaxf(v.w, 0.f);
            }
            if (OUTH) {
                ((uint2*)out)[row * 16 + c] = f4_to_h4(v);
            } else {
                ((float4*)out)[row * 16 + c] = v;
            }
        }
    }
}

// ---------------- mean pool per graph (batch is sorted) ----------------
__device__ __forceinline__ int lower_bound_batch(const int* b, int val) {
    int lo = 0, hi = NN;
    while (lo < hi) {
        int mid = (lo + hi) >> 1;
        if (b[mid] < val) lo = mid + 1; else hi = mid;
    }
    return lo;
}

__global__ void pool_kernel(const float* __restrict__ h, const int* __restrict__ batch) {
    int g = blockIdx.x;
    __shared__ int s_lo, s_hi;
    if (threadIdx.x == 0) {
        s_lo = lower_bound_batch(batch, g);
        s_hi = lower_bound_batch(batch, g + 1);
    }
    __syncthreads();
    int lo = s_lo, hi = s_hi;
    int f = threadIdx.x & 63;
    int part = threadIdx.x >> 6;
    float acc = 0.f;
    for (int i = lo + part; i < hi; i += 4) acc += h[i * 64 + f];
    __shared__ float sh[4][64];
    sh[part][f] = acc;
    __syncthreads();
    if (part == 0) {
        float s = sh[0][f] + sh[1][f] + sh[2][f] + sh[3][f];
        float cnt = (float)(hi - lo);
        g_pool[g * 64 + f] = s / fmaxf(cnt, 1.f);
    }
}

// ---------------- final MLP ----------------
__global__ void mlp_kernel(const float* __restrict__ Wl1, const float* __restrict__ bl1,
                           const float* __restrict__ Wl2, const float* __restrict__ bl2,
                           float* __restrict__ out) {
    __shared__ float sp[GG * 64];
    __shared__ float sh1[GG * 32];
    int tid = threadIdx.x;
    for (int i = tid; i < GG * 64; i += 256) sp[i] = g_pool[i];
    __syncthreads();
    for (int i = tid; i < GG * 32; i += 256) {
        int g = i >> 5, c = i & 31;
        float s = bl1[c];
        #pragma unroll 8
        for (int k = 0; k < 64; k++) s += sp[g * 64 + k] * Wl1[k * 32 + c];
        sh1[i] = fmaxf(s, 0.f);
    }
    __syncthreads();
    for (int i = tid; i < GG * CC; i += 256) {
        int g = i / CC, c = i % CC;
        float s = bl2[c];
        #pragma unroll
        for (int k = 0; k < 32; k++) s += sh1[g * 32 + k] * Wl2[k * CC + c];
        out[i] = s;
    }
}

// ---------------- launcher ----------------
extern "C" void kernel_launch(void* const* d_in, const int* in_sizes, int n_in,
                              void* d_out, int out_size) {
    const float* x    = (const float*)d_in[0];
    const int*   ei   = (const int*)d_in[1];
    const float* attr = (const float*)d_in[2];
    const int*   bat  = (const int*)d_in[3];
    const float* W1 = (const float*)d_in[4];
    const float* b1 = (const float*)d_in[5];
    const float* W2 = (const float*)d_in[6];
    const float* b2 = (const float*)d_in[7];
    const float* W3 = (const float*)d_in[8];
    const float* b3 = (const float*)d_in[9];
    const float* Wl1 = (const float*)d_in[10];
    const float* bl1 = (const float*)d_in[11];
    const float* Wl2 = (const float*)d_in[12];
    const float* bl2 = (const float*)d_in[13];
    float* out = (float*)d_out;

    uint2 *xh, *T1, *T2, *H0, *H1;
    float *Hf;
    void* zp;
    cudaGetSymbolAddress((void**)&xh, g_xh);
    cudaGetSymbolAddress((void**)&T1, g_T1);
    cudaGetSymbolAddress((void**)&T2, g_T2);
    cudaGetSymbolAddress((void**)&H0, g_H0);
    cudaGetSymbolAddress((void**)&H1, g_H1);
    cudaGetSymbolAddress((void**)&Hf, g_Hf);
    cudaGetSymbolAddress(&zp, g_zero);

    const int SMEM = 64 * SA_STRIDE * 2 + 192 * 64 * 2;  // 26624 + 24576 = 51200
    cudaFuncSetAttribute((const void*)gemm3_kernel<true, true>,
                         cudaFuncAttributeMaxDynamicSharedMemorySize, SMEM);
    cudaFuncSetAttribute((const void*)gemm3_kernel<false, false>,
                         cudaFuncAttributeMaxDynamicSharedMemorySize, SMEM);

    const int NB_E4 = (EE / 4 + 255) / 256;
    const int NB_P = (NN * 16 + 255) / 256;   // 16 threads per row
    const int NB_G = (NN + 63) / 64;
    const int NB_C = (NN * 16 + 255) / 256;

    cudaMemsetAsync(zp, 0, ZERO_BYTES);
    deg_kernel<<<NB_E4, 256>>>(ei, attr);
    cvt_kernel<<<NB_C, 256>>>((const float4*)x);
    scan_kernel<<<NBLK, 1024>>>();
    fill_kernel<<<NB_E4, 256>>>(ei, attr);

    // Layer 1: T1 = S*xh, U = S*T1, H0 = relu([xh|T1|U] @ folded(W1) + b1)
    prop_kernel<<<NB_P, 256>>>(xh, T1);
    prop_kernel<<<NB_P, 256>>>(T1, T2);
    gemm3_kernel<true, true><<<NB_G, 256, SMEM>>>(xh, T1, T2, W1, b1, H0);
    // Layer 2
    prop_kernel<<<NB_P, 256>>>(H0, T1);
    prop_kernel<<<NB_P, 256>>>(T1, T2);
    gemm3_kernel<true, true><<<NB_G, 256, SMEM>>>(H0, T1, T2, W2, b2, H1);
    // Layer 3 (fp32 output for pooling)
    prop_kernel<<<NB_P, 256>>>(H1, T1);
    prop_kernel<<<NB_P, 256>>>(T1, T2);
    gemm3_kernel<false, false><<<NB_G, 256, SMEM>>>(H1, T1, T2, W3, b3, Hf);

    pool_kernel<<<GG, 256>>>(Hf, bat);
    mlp_kernel<<<1, 256>>>(Wl1, bl1, Wl2, bl2, out);
}

// round 10
// speedup vs baseline: 1.2155x; 1.0059x over previous
#include <cuda_runtime.h>
#include <cuda_fp16.h>
#include <mma.h>

using namespace nvcuda;

#define NN 50000
#define EE 800000
#define F 64
#define GG 64
#define CC 10
#define NBLK 49   // ceil(NN/1024)

typedef unsigned long long ull;

// ---------------- scratch (device globals; no allocation allowed) ----------------
#define WDEG_OFF   0
#define DEGCNT_OFF (NN * 4)
#define STATE_OFF  (2 * NN * 4)
#define ZERO_BYTES (STATE_OFF + 64 * 8)
__device__ __align__(16) unsigned char g_zero[ZERO_BYTES];

__device__ __align__(16) float  g_dinv[NN];
__device__ __align__(16) int    g_rowptr[NN + 1];
__device__ __align__(16) int    g_fill[NN];
__device__ __align__(16) int2   g_edges[EE];     // (col, bitcast(norm)) sorted by row
__device__ __align__(16) __half g_xh[NN * F];    // fp16 copy of x
__device__ __align__(16) __half g_T1[NN * F];
__device__ __align__(16) __half g_T2[NN * F];
__device__ __align__(16) __half g_H0[NN * F];
__device__ __align__(16) __half g_H1[NN * F];
__device__ __align__(16) float  g_Hf[NN * F];    // fp32 final layer output
__device__ __align__(16) float  g_pool[GG * F];
__device__ __align__(16) __half g_Wf[3 * 192 * 64];  // pre-folded fp16 weights per layer

// fp16 pack/unpack helpers (8 bytes = 4 features)
__device__ __forceinline__ float4 h4_to_f4(uint2 u) {
    float2 a = __half22float2(*reinterpret_cast<const __half2*>(&u.x));
    float2 b = __half22float2(*reinterpret_cast<const __half2*>(&u.y));
    return make_float4(a.x, a.y, b.x, b.y);
}
__device__ __forceinline__ uint2 f4_to_h4(float4 v) {
    __half2 a = __floats2half2_rn(v.x, v.y);
    __half2 b = __floats2half2_rn(v.z, v.w);
    uint2 u;
    u.x = *reinterpret_cast<unsigned*>(&a);
    u.y = *reinterpret_cast<unsigned*>(&b);
    return u;
}

// ---------------- build: 2 edges/thread ----------------
__global__ void deg_kernel(const int* __restrict__ ei, const float* __restrict__ attr) {
    float* wdeg = (float*)(g_zero + WDEG_OFF);
    int* degcnt = (int*)(g_zero + DEGCNT_OFF);
    int t = blockIdx.x * blockDim.x + threadIdx.x;
    int e0 = t * 2;
    if (e0 + 1 < EE) {
        int2 r2 = *(const int2*)(ei + e0);
        float2 a2 = *(const float2*)(attr + e0);
        atomicAdd(&wdeg[r2.x], a2.x); atomicAdd(&degcnt[r2.x], 1);
        atomicAdd(&wdeg[r2.y], a2.y); atomicAdd(&degcnt[r2.y], 1);
    } else if (e0 < EE) {
        int r = ei[e0];
        atomicAdd(&wdeg[r], attr[e0]);
        atomicAdd(&degcnt[r], 1);
    }
}

// Single-kernel scan + dinv + rowptr/fill init. 49 blocks x 1024 (one wave).
__global__ void scan_kernel() {
    float* wdeg = (float*)(g_zero + WDEG_OFF);
    int* degcnt = (int*)(g_zero + DEGCNT_OFF);
    volatile ull* state = (volatile ull*)(g_zero + STATE_OFF);

    int tid = threadIdx.x;
    int b = blockIdx.x;
    int i = b * 1024 + tid;
    int v = (i < NN) ? degcnt[i] : 0;

    if (i < NN) {
        float d = wdeg[i];
        g_dinv[i] = (d > 0.f) ? rsqrtf(d) : 0.f;
    }

    int lane = tid & 31, wid = tid >> 5;
    int x = v;
    #pragma unroll
    for (int o = 1; o < 32; o <<= 1) {
        int y = __shfl_up_sync(0xFFFFFFFFu, x, o);
        if (lane >= o) x += y;
    }
    __shared__ int ws[32];
    __shared__ int s_prefix;
    if (lane == 31) ws[wid] = x;
    __syncthreads();
    if (wid == 0) {
        int s = ws[lane];
        #pragma unroll
        for (int o = 1; o < 32; o <<= 1) {
            int y = __shfl_up_sync(0xFFFFFFFFu, s, o);
            if (lane >= o) s += y;
        }
        ws[lane] = s;
    }
    __syncthreads();
    int blocksum = ws[31];

    if (tid == 0) {
        atomicExch((ull*)&state[b], (1ull << 32) | (unsigned)blocksum);
    }
    if (tid < 32) {
        int acc = 0;
        for (int p = tid; p < b; p += 32) {
            ull sv;
            do { sv = state[p]; } while ((sv >> 32) == 0);
            acc += (int)(unsigned)sv;
        }
        #pragma unroll
        for (int o = 16; o > 0; o >>= 1) acc += __shfl_down_sync(0xFFFFFFFFu, acc, o);
        if (tid == 0) s_prefix = acc;
    }
    __syncthreads();

    int excl = x - v + (wid > 0 ? ws[wid - 1] : 0);
    if (i < NN) {
        int r = excl + s_prefix;
        g_rowptr[i] = r;
        g_fill[i]   = r;
    }
    if (b == 0 && tid == 0) g_rowptr[NN] = EE;
}

__global__ void fill_kernel(const int* __restrict__ ei, const float* __restrict__ attr) {
    int t = blockIdx.x * blockDim.x + threadIdx.x;
    int e0 = t * 2;
    if (e0 + 1 < EE) {
        int2 r2 = *(const int2*)(ei + e0);
        int2 c2 = *(const int2*)(ei + EE + e0);
        float2 a2 = *(const float2*)(attr + e0);
        float w0 = -a2.x * g_dinv[r2.x] * g_dinv[c2.x];
        float w1 = -a2.y * g_dinv[r2.y] * g_dinv[c2.y];
        int p0 = atomicAdd(&g_fill[r2.x], 1);
        int p1 = atomicAdd(&g_fill[r2.y], 1);
        g_edges[p0] = make_int2(c2.x, __float_as_int(w0));
        g_edges[p1] = make_int2(c2.y, __float_as_int(w1));
    } else if (e0 < EE) {
        int r = ei[e0];
        int c = ei[EE + e0];
        float w = -attr[e0] * g_dinv[r] * g_dinv[c];
        int pos = atomicAdd(&g_fill[r], 1);
        g_edges[pos] = make_int2(c, __float_as_int(w));
    }
}

// ---------------- x -> fp16 copy ----------------
__global__ void cvt_kernel(const float4* __restrict__ in) {
    int i = blockIdx.x * blockDim.x + threadIdx.x;
    if (i < NN * 16) {
        ((uint2*)g_xh)[i] = f4_to_h4(in[i]);
    }
}

// ---------------- W pre-fold: layer b -> fp16 [W0-W2; W1; 2*W2] (192x64) ----------------
__global__ void wprep_kernel(const float* __restrict__ W1, const float* __restrict__ W2,
                             const float* __restrict__ W3) {
    int b = blockIdx.x;
    const float* W = (b == 0) ? W1 : (b == 1) ? W2 : W3;
    __half* dst = g_Wf + b * 192 * 64;
    int tid = threadIdx.x;
    for (int i = tid; i < 1024; i += 256) {
        int k = i >> 4, c = i & 15;
        float4 w0 = ((const float4*)W)[i];
        float4 w1 = ((const float4*)W)[1024 + i];
        float4 w2 = ((const float4*)W)[2048 + i];
        float4 f0 = make_float4(w0.x - w2.x, w0.y - w2.y, w0.z - w2.z, w0.w - w2.w);
        float4 f2 = make_float4(2.f * w2.x, 2.f * w2.y, 2.f * w2.z, 2.f * w2.w);
        *(uint2*)&dst[k * 64 + c * 4]         = f4_to_h4(f0);
        *(uint2*)&dst[(64 + k) * 64 + c * 4]  = f4_to_h4(w1);
        *(uint2*)&dst[(128 + k) * 64 + c * 4] = f4_to_h4(f2);
    }
}

// ---------------- sparse propagation: half-warp (16 lanes) per row, fp16, 8x unroll ----
__global__ void prop_kernel(const uint2* __restrict__ in, uint2* __restrict__ out) {
    int idx = blockIdx.x * blockDim.x + threadIdx.x;
    int row = idx >> 4;
    if (row >= NN) return;
    int l = idx & 15;
    int s = g_rowptr[row], e = g_rowptr[row + 1];

    float4 A = make_float4(0.f, 0.f, 0.f, 0.f);
    float4 B = make_float4(0.f, 0.f, 0.f, 0.f);
    float4 Cq = make_float4(0.f, 0.f, 0.f, 0.f);
    float4 D = make_float4(0.f, 0.f, 0.f, 0.f);
    int j = s;
    for (; j + 8 <= e; j += 8) {
        int2 e0 = g_edges[j];
        int2 e1 = g_edges[j + 1];
        int2 e2 = g_edges[j + 2];
        int2 e3 = g_edges[j + 3];
        int2 e4 = g_edges[j + 4];
        int2 e5 = g_edges[j + 5];
        int2 e6 = g_edges[j + 6];
        int2 e7 = g_edges[j + 7];
        uint2 u0 = in[e0.x * 16 + l];
        uint2 u1 = in[e1.x * 16 + l];
        uint2 u2 = in[e2.x * 16 + l];
        uint2 u3 = in[e3.x * 16 + l];
        uint2 u4 = in[e4.x * 16 + l];
        uint2 u5 = in[e5.x * 16 + l];
        uint2 u6 = in[e6.x * 16 + l];
        uint2 u7 = in[e7.x * 16 + l];
        float w0 = __int_as_float(e0.y);
        float w1 = __int_as_float(e1.y);
        float w2 = __int_as_float(e2.y);
        float w3 = __int_as_float(e3.y);
        float w4 = __int_as_float(e4.y);
        float w5 = __int_as_float(e5.y);
        float w6 = __int_as_float(e6.y);
        float w7 = __int_as_float(e7.y);
        float4 v0 = h4_to_f4(u0);
        float4 v1 = h4_to_f4(u1);
        float4 v2 = h4_to_f4(u2);
        float4 v3 = h4_to_f4(u3);
        float4 v4 = h4_to_f4(u4);
        float4 v5 = h4_to_f4(u5);
        float4 v6 = h4_to_f4(u6);
        float4 v7 = h4_to_f4(u7);
        A.x = fmaf(w0, v0.x, A.x); A.y = fmaf(w0, v0.y, A.y);
        A.z = fmaf(w0, v0.z, A.z); A.w = fmaf(w0, v0.w, A.w);
        B.x = fmaf(w1, v1.x, B.x); B.y = fmaf(w1, v1.y, B.y);
        B.z = fmaf(w1, v1.z, B.z); B.w = fmaf(w1, v1.w, B.w);
        Cq.x = fmaf(w2, v2.x, Cq.x); Cq.y = fmaf(w2, v2.y, Cq.y);
        Cq.z = fmaf(w2, v2.z, Cq.z); Cq.w = fmaf(w2, v2.w, Cq.w);
        D.x = fmaf(w3, v3.x, D.x); D.y = fmaf(w3, v3.y, D.y);
        D.z = fmaf(w3, v3.z, D.z); D.w = fmaf(w3, v3.w, D.w);
        A.x = fmaf(w4, v4.x, A.x); A.y = fmaf(w4, v4.y, A.y);
        A.z = fmaf(w4, v4.z, A.z); A.w = fmaf(w4, v4.w, A.w);
        B.x = fmaf(w5, v5.x, B.x); B.y = fmaf(w5, v5.y, B.y);
        B.z = fmaf(w5, v5.z, B.z); B.w = fmaf(w5, v5.w, B.w);
        Cq.x = fmaf(w6, v6.x, Cq.x); Cq.y = fmaf(w6, v6.y, Cq.y);
        Cq.z = fmaf(w6, v6.z, Cq.z); Cq.w = fmaf(w6, v6.w, Cq.w);
        D.x = fmaf(w7, v7.x, D.x); D.y = fmaf(w7, v7.y, D.y);
        D.z = fmaf(w7, v7.z, D.z); D.w = fmaf(w7, v7.w, D.w);
    }
    for (; j < e; j++) {
        int2 ed = g_edges[j];
        uint2 u = in[ed.x * 16 + l];
        float w = __int_as_float(ed.y);
        float4 v = h4_to_f4(u);
        A.x = fmaf(w, v.x, A.x); A.y = fmaf(w, v.y, A.y);
        A.z = fmaf(w, v.z, A.z); A.w = fmaf(w, v.w, A.w);
    }
    float4 r;
    r.x = (A.x + B.x) + (Cq.x + D.x);
    r.y = (A.y + B.y) + (Cq.y + D.y);
    r.z = (A.z + B.z) + (Cq.z + D.z);
    r.w = (A.w + B.w) + (Cq.w + D.w);
    out[row * 16 + l] = f4_to_h4(r);
}

// ---------------- tensor-core GEMM: out = relu?([x|T1|U] @ Wf + b) ----------------
// A: 64x192 fp16 (3 mats concatenated in K), B: pre-folded 192x64 fp16.
#define SA_STRIDE 208   // 192 + 16 padding
template <bool RELU, bool OUTH>
__global__ __launch_bounds__(256, 2) void gemm3_kernel(
    const uint2* __restrict__ x0, const uint2* __restrict__ x1, const uint2* __restrict__ x2,
    const __half* __restrict__ Wf, const float* __restrict__ b, void* __restrict__ out) {
    extern __shared__ char smem[];
    __half* sA = (__half*)smem;                          // 64 x SA_STRIDE fp16 = 26624 B
    __half* sB = (__half*)(smem + 64 * SA_STRIDE * 2);   // 192 x 64 fp16 = 24576 B
    float*  sC = (float*)smem;                           // reused after MMA: 64x64 fp32

    int tid = threadIdx.x;
    int row0 = blockIdx.x * 64;

    // stage A (fp16 passthrough)
    #pragma unroll
    for (int m = 0; m < 3; m++) {
        const uint2* src = (m == 0) ? x0 : (m == 1) ? x1 : x2;
        for (int i = tid; i < 1024; i += 256) {
            int r = i >> 4, c = i & 15;
            int row = row0 + r;
            uint2 v = (row < NN) ? src[row * 16 + c] : make_uint2(0u, 0u);
            *(uint2*)&sA[r * SA_STRIDE + m * 64 + c * 4] = v;
        }
    }
    // stage B: straight copy of pre-folded fp16 weights (24576 B = 1536 uint4)
    {
        uint4* d = (uint4*)sB;
        const uint4* g = (const uint4*)Wf;
        #pragma unroll
        for (int i = tid; i < 1536; i += 256) d[i] = g[i];
    }
    __syncthreads();

    // MMA: warp w -> tiles (wm, wn) and (wm+2, wn)
    int w = tid >> 5;
    int wm = w >> 2;   // 0..1
    int wn = w & 3;    // 0..3
    wmma::fragment<wmma::accumulator, 16, 16, 16, float> acc0, acc1;
    wmma::fill_fragment(acc0, 0.f);
    wmma::fill_fragment(acc1, 0.f);
    #pragma unroll
    for (int k = 0; k < 192; k += 16) {
        wmma::fragment<wmma::matrix_a, 16, 16, 16, __half, wmma::row_major> a0, a1;
        wmma::fragment<wmma::matrix_b, 16, 16, 16, __half, wmma::row_major> bf;
        wmma::load_matrix_sync(a0, sA + (wm * 16) * SA_STRIDE + k, SA_STRIDE);
        wmma::load_matrix_sync(a1, sA + (wm * 16 + 32) * SA_STRIDE + k, SA_STRIDE);
        wmma::load_matrix_sync(bf, sB + k * 64 + wn * 16, 64);
        wmma::mma_sync(acc0, a0, bf, acc0);
        wmma::mma_sync(acc1, a1, bf, acc1);
    }
    __syncthreads();  // done reading sA; reuse as sC
    wmma::store_matrix_sync(sC + (wm * 16) * 64 + wn * 16, acc0, 64, wmma::mem_row_major);
    wmma::store_matrix_sync(sC + (wm * 16 + 32) * 64 + wn * 16, acc1, 64, wmma::mem_row_major);
    __syncthreads();

    // epilogue: bias + relu + store
    for (int i = tid; i < 1024; i += 256) {
        int r = i >> 4, c = i & 15;
        int row = row0 + r;
        if (row < NN) {
            float4 v = ((const float4*)sC)[i];
            float4 bias = ((const float4*)b)[c];
            v.x += bias.x; v.y += bias.y; v.z += bias.z; v.w += bias.w;
            if (RELU) {
                v.x = fmaxf(v.x, 0.f); v.y = fmaxf(v.y, 0.f);
                v.z = fmaxf(v.z, 0.f); v.w = fmaxf(v.w, 0.f);
            }
            if (OUTH) {
                ((uint2*)out)[row * 16 + c] = f4_to_h4(v);
            } else {
                ((float4*)out)[row * 16 + c] = v;
            }
        }
    }
}

// ---------------- mean pool per graph (batch is sorted) ----------------
__device__ __forceinline__ int lower_bound_batch(const int* b, int val) {
    int lo = 0, hi = NN;
    while (lo < hi) {
        int mid = (lo + hi) >> 1;
        if (b[mid] < val) lo = mid + 1; else hi = mid;
    }
    return lo;
}

__global__ void pool_kernel(const float* __restrict__ h, const int* __restrict__ batch) {
    int g = blockIdx.x;
    __shared__ int s_lo, s_hi;
    if (threadIdx.x == 0) {
        s_lo = lower_bound_batch(batch, g);
        s_hi = lower_bound_batch(batch, g + 1);
    }
    __syncthreads();
    int lo = s_lo, hi = s_hi;
    int f = threadIdx.x & 63;
    int part = threadIdx.x >> 6;
    float acc = 0.f;
    for (int i = lo + part; i < hi; i += 4) acc += h[i * 64 + f];
    __shared__ float sh[4][64];
    sh[part][f] = acc;
    __syncthreads();
    if (part == 0) {
        float s = sh[0][f] + sh[1][f] + sh[2][f] + sh[3][f];
        float cnt = (float)(hi - lo);
        g_pool[g * 64 + f] = s / fmaxf(cnt, 1.f);
    }
}

// ---------------- final MLP ----------------
__global__ void mlp_kernel(const float* __restrict__ Wl1, const float* __restrict__ bl1,
                           const float* __restrict__ Wl2, const float* __restrict__ bl2,
                           float* __restrict__ out) {
    __shared__ float sp[GG * 64];
    __shared__ float sh1[GG * 32];
    int tid = threadIdx.x;
    for (int i = tid; i < GG * 64; i += 256) sp[i] = g_pool[i];
    __syncthreads();
    for (int i = tid; i < GG * 32; i += 256) {
        int g = i >> 5, c = i & 31;
        float s = bl1[c];
        #pragma unroll 8
        for (int k = 0; k < 64; k++) s += sp[g * 64 + k] * Wl1[k * 32 + c];
        sh1[i] = fmaxf(s, 0.f);
    }
    __syncthreads();
    for (int i = tid; i < GG * CC; i += 256) {
        int g = i / CC, c = i % CC;
        float s = bl2[c];
        #pragma unroll
        for (int k = 0; k < 32; k++) s += sh1[g * 32 + k] * Wl2[k * CC + c];
        out[i] = s;
    }
}

// ---------------- launcher ----------------
extern "C" void kernel_launch(void* const* d_in, const int* in_sizes, int n_in,
                              void* d_out, int out_size) {
    const float* x    = (const float*)d_in[0];
    const int*   ei   = (const int*)d_in[1];
    const float* attr = (const float*)d_in[2];
    const int*   bat  = (const int*)d_in[3];
    const float* W1 = (const float*)d_in[4];
    const float* b1 = (const float*)d_in[5];
    const float* W2 = (const float*)d_in[6];
    const float* b2 = (const float*)d_in[7];
    const float* W3 = (const float*)d_in[8];
    const float* b3 = (const float*)d_in[9];
    const float* Wl1 = (const float*)d_in[10];
    const float* bl1 = (const float*)d_in[11];
    const float* Wl2 = (const float*)d_in[12];
    const float* bl2 = (const float*)d_in[13];
    float* out = (float*)d_out;

    uint2 *xh, *T1, *T2, *H0, *H1;
    __half* Wf;
    float *Hf;
    void* zp;
    cudaGetSymbolAddress((void**)&xh, g_xh);
    cudaGetSymbolAddress((void**)&T1, g_T1);
    cudaGetSymbolAddress((void**)&T2, g_T2);
    cudaGetSymbolAddress((void**)&H0, g_H0);
    cudaGetSymbolAddress((void**)&H1, g_H1);
    cudaGetSymbolAddress((void**)&Hf, g_Hf);
    cudaGetSymbolAddress((void**)&Wf, g_Wf);
    cudaGetSymbolAddress(&zp, g_zero);

    const int SMEM = 64 * SA_STRIDE * 2 + 192 * 64 * 2;  // 26624 + 24576 = 51200
    cudaFuncSetAttribute((const void*)gemm3_kernel<true, true>,
                         cudaFuncAttributeMaxDynamicSharedMemorySize, SMEM);
    cudaFuncSetAttribute((const void*)gemm3_kernel<false, false>,
                         cudaFuncAttributeMaxDynamicSharedMemorySize, SMEM);

    const int NB_E2 = (EE / 2 + 255) / 256;
    const int NB_P = (NN * 16 + 255) / 256;   // 16 threads per row
    const int NB_G = (NN + 63) / 64;
    const int NB_C = (NN * 16 + 255) / 256;

    cudaMemsetAsync(zp, 0, ZERO_BYTES);
    deg_kernel<<<NB_E2, 256>>>(ei, attr);
    cvt_kernel<<<NB_C, 256>>>((const float4*)x);
    wprep_kernel<<<3, 256>>>(W1, W2, W3);
    scan_kernel<<<NBLK, 1024>>>();
    fill_kernel<<<NB_E2, 256>>>(ei, attr);

    // Layer 1: T1 = S*xh, U = S*T1, H0 = relu([xh|T1|U] @ Wf1 + b1)
    prop_kernel<<<NB_P, 256>>>(xh, T1);
    prop_kernel<<<NB_P, 256>>>(T1, T2);
    gemm3_kernel<true, true><<<NB_G, 256, SMEM>>>(xh, T1, T2, Wf, b1, H0);
    // Layer 2
    prop_kernel<<<NB_P, 256>>>(H0, T1);
    prop_kernel<<<NB_P, 256>>>(T1, T2);
    gemm3_kernel<true, true><<<NB_G, 256, SMEM>>>(H0, T1, T2, Wf + 192 * 64, b2, H1);
    // Layer 3 (fp32 output for pooling)
    prop_kernel<<<NB_P, 256>>>(H1, T1);
    prop_kernel<<<NB_P, 256>>>(T1, T2);
    gemm3_kernel<false, false><<<NB_G, 256, SMEM>>>(H1, T1, T2, Wf + 2 * 192 * 64, b3, Hf);

    pool_kernel<<<GG, 256>>>(Hf, bat);
    mlp_kernel<<<1, 256>>>(Wl1, bl1, Wl2, bl2, out);
}

// round 11
// speedup vs baseline: 1.2742x; 1.0483x over previous
#include <cuda_runtime.h>
#include <cuda_fp16.h>
#include <mma.h>

using namespace nvcuda;

#define NN 50000
#define EE 800000
#define F 64
#define GG 64
#define CC 10
#define NBLK 49   // ceil(NN/1024)

typedef unsigned long long ull;

// ---------------- scratch (device globals; no allocation allowed) ----------------
#define WDEG_OFF    0
#define DEGCNT_OFF  (NN * 4)
#define STATE_OFF   (2 * NN * 4)
#define POOLCNT_OFF (STATE_OFF + 64 * 8)
#define ZERO_BYTES  (POOLCNT_OFF + 16)
__device__ __align__(16) unsigned char g_zero[ZERO_BYTES];

__device__ __align__(16) float  g_dinv[NN];
__device__ __align__(16) int    g_rowptr[NN + 1];
__device__ __align__(16) int    g_fill[NN];
__device__ __align__(16) int2   g_edges[EE];     // (col, bitcast(norm)) sorted by row
__device__ __align__(16) __half g_T1[NN * F];
__device__ __align__(16) __half g_T2[NN * F];
__device__ __align__(16) __half g_H0[NN * F];
__device__ __align__(16) __half g_H1[NN * F];
__device__ __align__(16) float  g_Hf[NN * F];    // fp32 final layer output
__device__ __align__(16) float  g_pool[GG * F];
__device__ __align__(16) __half g_Wf[3 * 192 * 64];  // pre-folded fp16 weights per layer

// fp16 pack/unpack helpers (8 bytes = 4 features)
__device__ __forceinline__ float4 h4_to_f4(uint2 u) {
    float2 a = __half22float2(*reinterpret_cast<const __half2*>(&u.x));
    float2 b = __half22float2(*reinterpret_cast<const __half2*>(&u.y));
    return make_float4(a.x, a.y, b.x, b.y);
}
__device__ __forceinline__ uint2 f4_to_h4(float4 v) {
    __half2 a = __floats2half2_rn(v.x, v.y);
    __half2 b = __floats2half2_rn(v.z, v.w);
    uint2 u;
    u.x = *reinterpret_cast<unsigned*>(&a);
    u.y = *reinterpret_cast<unsigned*>(&b);
    return u;
}

// ---------------- fused build: blocks 0-2 fold W, rest do degree (2 edges/thread) ----
__global__ void degw_kernel(const int* __restrict__ ei, const float* __restrict__ attr,
                            const float* __restrict__ W1, const float* __restrict__ W2,
                            const float* __restrict__ W3) {
    if (blockIdx.x < 3) {
        int b = blockIdx.x;
        const float* W = (b == 0) ? W1 : (b == 1) ? W2 : W3;
        __half* dst = g_Wf + b * 192 * 64;
        int tid = threadIdx.x;
        for (int i = tid; i < 1024; i += 256) {
            int k = i >> 4, c = i & 15;
            float4 w0 = ((const float4*)W)[i];
            float4 w1 = ((const float4*)W)[1024 + i];
            float4 w2 = ((const float4*)W)[2048 + i];
            float4 f0 = make_float4(w0.x - w2.x, w0.y - w2.y, w0.z - w2.z, w0.w - w2.w);
            float4 f2 = make_float4(2.f * w2.x, 2.f * w2.y, 2.f * w2.z, 2.f * w2.w);
            *(uint2*)&dst[k * 64 + c * 4]         = f4_to_h4(f0);
            *(uint2*)&dst[(64 + k) * 64 + c * 4]  = f4_to_h4(w1);
            *(uint2*)&dst[(128 + k) * 64 + c * 4] = f4_to_h4(f2);
        }
        return;
    }
    float* wdeg = (float*)(g_zero + WDEG_OFF);
    int* degcnt = (int*)(g_zero + DEGCNT_OFF);
    int t = (blockIdx.x - 3) * blockDim.x + threadIdx.x;
    int e0 = t * 2;
    if (e0 + 1 < EE) {
        int2 r2 = *(const int2*)(ei + e0);
        float2 a2 = *(const float2*)(attr + e0);
        atomicAdd(&wdeg[r2.x], a2.x); atomicAdd(&degcnt[r2.x], 1);
        atomicAdd(&wdeg[r2.y], a2.y); atomicAdd(&degcnt[r2.y], 1);
    } else if (e0 < EE) {
        int r = ei[e0];
        atomicAdd(&wdeg[r], attr[e0]);
        atomicAdd(&degcnt[r], 1);
    }
}

// Single-kernel scan + dinv + rowptr/fill init. 49 blocks x 1024 (one wave).
__global__ void scan_kernel() {
    float* wdeg = (float*)(g_zero + WDEG_OFF);
    int* degcnt = (int*)(g_zero + DEGCNT_OFF);
    volatile ull* state = (volatile ull*)(g_zero + STATE_OFF);

    int tid = threadIdx.x;
    int b = blockIdx.x;
    int i = b * 1024 + tid;
    int v = (i < NN) ? degcnt[i] : 0;

    if (i < NN) {
        float d = wdeg[i];
        g_dinv[i] = (d > 0.f) ? rsqrtf(d) : 0.f;
    }

    int lane = tid & 31, wid = tid >> 5;
    int x = v;
    #pragma unroll
    for (int o = 1; o < 32; o <<= 1) {
        int y = __shfl_up_sync(0xFFFFFFFFu, x, o);
        if (lane >= o) x += y;
    }
    __shared__ int ws[32];
    __shared__ int s_prefix;
    if (lane == 31) ws[wid] = x;
    __syncthreads();
    if (wid == 0) {
        int s = ws[lane];
        #pragma unroll
        for (int o = 1; o < 32; o <<= 1) {
            int y = __shfl_up_sync(0xFFFFFFFFu, s, o);
            if (lane >= o) s += y;
        }
        ws[lane] = s;
    }
    __syncthreads();
    int blocksum = ws[31];

    if (tid == 0) {
        atomicExch((ull*)&state[b], (1ull << 32) | (unsigned)blocksum);
    }
    if (tid < 32) {
        int acc = 0;
        for (int p = tid; p < b; p += 32) {
            ull sv;
            do { sv = state[p]; } while ((sv >> 32) == 0);
            acc += (int)(unsigned)sv;
        }
        #pragma unroll
        for (int o = 16; o > 0; o >>= 1) acc += __shfl_down_sync(0xFFFFFFFFu, acc, o);
        if (tid == 0) s_prefix = acc;
    }
    __syncthreads();

    int excl = x - v + (wid > 0 ? ws[wid - 1] : 0);
    if (i < NN) {
        int r = excl + s_prefix;
        g_rowptr[i] = r;
        g_fill[i]   = r;
    }
    if (b == 0 && tid == 0) g_rowptr[NN] = EE;
}

__global__ void fill_kernel(const int* __restrict__ ei, const float* __restrict__ attr) {
    int t = blockIdx.x * blockDim.x + threadIdx.x;
    int e0 = t * 2;
    if (e0 + 1 < EE) {
        int2 r2 = *(const int2*)(ei + e0);
        int2 c2 = *(const int2*)(ei + EE + e0);
        float2 a2 = *(const float2*)(attr + e0);
        float w0 = -a2.x * g_dinv[r2.x] * g_dinv[c2.x];
        float w1 = -a2.y * g_dinv[r2.y] * g_dinv[c2.y];
        int p0 = atomicAdd(&g_fill[r2.x], 1);
        int p1 = atomicAdd(&g_fill[r2.y], 1);
        g_edges[p0] = make_int2(c2.x, __float_as_int(w0));
        g_edges[p1] = make_int2(c2.y, __float_as_int(w1));
    } else if (e0 < EE) {
        int r = ei[e0];
        int c = ei[EE + e0];
        float w = -attr[e0] * g_dinv[r] * g_dinv[c];
        int pos = atomicAdd(&g_fill[r], 1);
        g_edges[pos] = make_int2(c, __float_as_int(w));
    }
}

// ---------------- sparse propagation: half-warp (16 lanes) per row ----------------
// F32IN: gather fp32 rows (layer-1 input x). Else fp16. Output fp16. fp32 accumulate.
// unroll 4, 2 accumulators, occupancy-first register budget.
template <bool F32IN>
__global__ __launch_bounds__(256, 5) void prop_kernel(const void* __restrict__ in_,
                                                      uint2* __restrict__ out) {
    int idx = blockIdx.x * blockDim.x + threadIdx.x;
    int row = idx >> 4;
    if (row >= NN) return;
    int l = idx & 15;
    int s = g_rowptr[row], e = g_rowptr[row + 1];
    const uint2* inh = (const uint2*)in_;
    const float4* inf = (const float4*)in_;

    float4 A = make_float4(0.f, 0.f, 0.f, 0.f);
    float4 B = make_float4(0.f, 0.f, 0.f, 0.f);
    int j = s;
    for (; j + 4 <= e; j += 4) {
        int2 e0 = g_edges[j];
        int2 e1 = g_edges[j + 1];
        int2 e2 = g_edges[j + 2];
        int2 e3 = g_edges[j + 3];
        float4 v0, v1, v2, v3;
        if (F32IN) {
            v0 = inf[e0.x * 16 + l];
            v1 = inf[e1.x * 16 + l];
            v2 = inf[e2.x * 16 + l];
            v3 = inf[e3.x * 16 + l];
        } else {
            uint2 u0 = inh[e0.x * 16 + l];
            uint2 u1 = inh[e1.x * 16 + l];
            uint2 u2 = inh[e2.x * 16 + l];
            uint2 u3 = inh[e3.x * 16 + l];
            v0 = h4_to_f4(u0);
            v1 = h4_to_f4(u1);
            v2 = h4_to_f4(u2);
            v3 = h4_to_f4(u3);
        }
        float w0 = __int_as_float(e0.y);
        float w1 = __int_as_float(e1.y);
        float w2 = __int_as_float(e2.y);
        float w3 = __int_as_float(e3.y);
        A.x = fmaf(w0, v0.x, A.x); A.y = fmaf(w0, v0.y, A.y);
        A.z = fmaf(w0, v0.z, A.z); A.w = fmaf(w0, v0.w, A.w);
        B.x = fmaf(w1, v1.x, B.x); B.y = fmaf(w1, v1.y, B.y);
        B.z = fmaf(w1, v1.z, B.z); B.w = fmaf(w1, v1.w, B.w);
        A.x = fmaf(w2, v2.x, A.x); A.y = fmaf(w2, v2.y, A.y);
        A.z = fmaf(w2, v2.z, A.z); A.w = fmaf(w2, v2.w, A.w);
        B.x = fmaf(w3, v3.x, B.x); B.y = fmaf(w3, v3.y, B.y);
        B.z = fmaf(w3, v3.z, B.z); B.w = fmaf(w3, v3.w, B.w);
    }
    for (; j < e; j++) {
        int2 ed = g_edges[j];
        float4 v;
        if (F32IN) {
            v = inf[ed.x * 16 + l];
        } else {
            v = h4_to_f4(inh[ed.x * 16 + l]);
        }
        float w = __int_as_float(ed.y);
        A.x = fmaf(w, v.x, A.x); A.y = fmaf(w, v.y, A.y);
        A.z = fmaf(w, v.z, A.z); A.w = fmaf(w, v.w, A.w);
    }
    float4 r = make_float4(A.x + B.x, A.y + B.y, A.z + B.z, A.w + B.w);
    out[row * 16 + l] = f4_to_h4(r);
}

// ---------------- tensor-core GEMM: out = relu?([x|T1|U] @ Wf + b) ----------------
// A: 64x192 fp16 (x0 may be fp32 source, converted in staging), B: pre-folded 192x64 fp16.
#define SA_STRIDE 208   // 192 + 16 padding
template <bool RELU, bool OUTH, bool X0F32>
__global__ __launch_bounds__(256, 2) void gemm3_kernel(
    const void* __restrict__ x0, const uint2* __restrict__ x1, const uint2* __restrict__ x2,
    const __half* __restrict__ Wf, const float* __restrict__ b, void* __restrict__ out) {
    extern __shared__ char smem[];
    __half* sA = (__half*)smem;                          // 64 x SA_STRIDE fp16 = 26624 B
    __half* sB = (__half*)(smem + 64 * SA_STRIDE * 2);   // 192 x 64 fp16 = 24576 B
    float*  sC = (float*)smem;                           // reused after MMA: 64x64 fp32

    int tid = threadIdx.x;
    int row0 = blockIdx.x * 64;

    // stage A slot 0 (x)
    for (int i = tid; i < 1024; i += 256) {
        int r = i >> 4, c = i & 15;
        int row = row0 + r;
        uint2 v;
        if (X0F32) {
            float4 f = (row < NN) ? ((const float4*)x0)[row * 16 + c]
                                  : make_float4(0.f, 0.f, 0.f, 0.f);
            v = f4_to_h4(f);
        } else {
            v = (row < NN) ? ((const uint2*)x0)[row * 16 + c] : make_uint2(0u, 0u);
        }
        *(uint2*)&sA[r * SA_STRIDE + c * 4] = v;
    }
    // stage A slots 1,2 (T1, U) fp16 passthrough
    #pragma unroll
    for (int m = 1; m < 3; m++) {
        const uint2* src = (m == 1) ? x1 : x2;
        for (int i = tid; i < 1024; i += 256) {
            int r = i >> 4, c = i & 15;
            int row = row0 + r;
            uint2 v = (row < NN) ? src[row * 16 + c] : make_uint2(0u, 0u);
            *(uint2*)&sA[r * SA_STRIDE + m * 64 + c * 4] = v;
        }
    }
    // stage B: straight copy of pre-folded fp16 weights (24576 B = 1536 uint4)
    {
        uint4* d = (uint4*)sB;
        const uint4* g = (const uint4*)Wf;
        #pragma unroll
        for (int i = tid; i < 1536; i += 256) d[i] = g[i];
    }
    __syncthreads();

    // MMA: warp w -> tiles (wm, wn) and (wm+2, wn)
    int w = tid >> 5;
    int wm = w >> 2;   // 0..1
    int wn = w & 3;    // 0..3
    wmma::fragment<wmma::accumulator, 16, 16, 16, float> acc0, acc1;
    wmma::fill_fragment(acc0, 0.f);
    wmma::fill_fragment(acc1, 0.f);
    #pragma unroll
    for (int k = 0; k < 192; k += 16) {
        wmma::fragment<wmma::matrix_a, 16, 16, 16, __half, wmma::row_major> a0, a1;
        wmma::fragment<wmma::matrix_b, 16, 16, 16, __half, wmma::row_major> bf;
        wmma::load_matrix_sync(a0, sA + (wm * 16) * SA_STRIDE + k, SA_STRIDE);
        wmma::load_matrix_sync(a1, sA + (wm * 16 + 32) * SA_STRIDE + k, SA_STRIDE);
        wmma::load_matrix_sync(bf, sB + k * 64 + wn * 16, 64);
        wmma::mma_sync(acc0, a0, bf, acc0);
        wmma::mma_sync(acc1, a1, bf, acc1);
    }
    __syncthreads();  // done reading sA; reuse as sC
    wmma::store_matrix_sync(sC + (wm * 16) * 64 + wn * 16, acc0, 64, wmma::mem_row_major);
    wmma::store_matrix_sync(sC + (wm * 16 + 32) * 64 + wn * 16, acc1, 64, wmma::mem_row_major);
    __syncthreads();

    // epilogue: bias + relu + store
    for (int i = tid; i < 1024; i += 256) {
        int r = i >> 4, c = i & 15;
        int row = row0 + r;
        if (row < NN) {
            float4 v = ((const float4*)sC)[i];
            float4 bias = ((const float4*)b)[c];
            v.x += bias.x; v.y += bias.y; v.z += bias.z; v.w += bias.w;
            if (RELU) {
                v.x = fmaxf(v.x, 0.f); v.y = fmaxf(v.y, 0.f);
                v.z = fmaxf(v.z, 0.f); v.w = fmaxf(v.w, 0.f);
            }
            if (OUTH) {
                ((uint2*)out)[row * 16 + c] = f4_to_h4(v);
            } else {
                ((float4*)out)[row * 16 + c] = v;
            }
        }
    }
}

// ---------------- mean pool per graph + last-block MLP ----------------
__device__ __forceinline__ int lower_bound_batch(const int* b, int val) {
    int lo = 0, hi = NN;
    while (lo < hi) {
        int mid = (lo + hi) >> 1;
        if (b[mid] < val) lo = mid + 1; else hi = mid;
    }
    return lo;
}

__global__ void pool_mlp_kernel(const float* __restrict__ h, const int* __restrict__ batch,
                                const float* __restrict__ Wl1, const float* __restrict__ bl1,
                                const float* __restrict__ Wl2, const float* __restrict__ bl2,
                                float* __restrict__ out) {
    int g = blockIdx.x;
    __shared__ int s_lo, s_hi;
    if (threadIdx.x == 0) {
        s_lo = lower_bound_batch(batch, g);
        s_hi = lower_bound_batch(batch, g + 1);
    }
    __syncthreads();
    int lo = s_lo, hi = s_hi;
    int f = threadIdx.x & 63;
    int part = threadIdx.x >> 6;
    float acc = 0.f;
    for (int i = lo + part; i < hi; i += 4) acc += h[i * 64 + f];
    __shared__ float sh[4][64];
    sh[part][f] = acc;
    __syncthreads();
    if (part == 0) {
        float s = sh[0][f] + sh[1][f] + sh[2][f] + sh[3][f];
        float cnt = (float)(hi - lo);
        g_pool[g * 64 + f] = s / fmaxf(cnt, 1.f);
    }
    // last-block pattern: final pool block runs the MLP
    __threadfence();
    __shared__ int s_last;
    __syncthreads();
    if (threadIdx.x == 0) {
        int* cnt = (int*)(g_zero + POOLCNT_OFF);
        s_last = (atomicAdd(cnt, 1) == GG - 1);
    }
    __syncthreads();
    if (!s_last) return;
    __threadfence();  // acquire: all g_pool writes visible

    __shared__ float sp[GG * 64];
    __shared__ float sh1[GG * 32];
    int tid = threadIdx.x;
    for (int i = tid; i < GG * 64; i += 256) sp[i] = g_pool[i];
    __syncthreads();
    for (int i = tid; i < GG * 32; i += 256) {
        int gg = i >> 5, c = i & 31;
        float s = bl1[c];
        #pragma unroll 8
        for (int k = 0; k < 64; k++) s += sp[gg * 64 + k] * Wl1[k * 32 + c];
        sh1[i] = fmaxf(s, 0.f);
    }
    __syncthreads();
    for (int i = tid; i < GG * CC; i += 256) {
        int gg = i / CC, c = i % CC;
        float s = bl2[c];
        #pragma unroll
        for (int k = 0; k < 32; k++) s += sh1[gg * 32 + k] * Wl2[k * CC + c];
        out[i] = s;
    }
}

// ---------------- launcher ----------------
extern "C" void kernel_launch(void* const* d_in, const int* in_sizes, int n_in,
                              void* d_out, int out_size) {
    const float* x    = (const float*)d_in[0];
    const int*   ei   = (const int*)d_in[1];
    const float* attr = (const float*)d_in[2];
    const int*   bat  = (const int*)d_in[3];
    const float* W1 = (const float*)d_in[4];
    const float* b1 = (const float*)d_in[5];
    const float* W2 = (const float*)d_in[6];
    const float* b2 = (const float*)d_in[7];
    const float* W3 = (const float*)d_in[8];
    const float* b3 = (const float*)d_in[9];
    const float* Wl1 = (const float*)d_in[10];
    const float* bl1 = (const float*)d_in[11];
    const float* Wl2 = (const float*)d_in[12];
    const float* bl2 = (const float*)d_in[13];
    float* out = (float*)d_out;

    uint2 *T1, *T2, *H0, *H1;
    __half* Wf;
    float *Hf;
    void* zp;
    cudaGetSymbolAddress((void**)&T1, g_T1);
    cudaGetSymbolAddress((void**)&T2, g_T2);
    cudaGetSymbolAddress((void**)&H0, g_H0);
    cudaGetSymbolAddress((void**)&H1, g_H1);
    cudaGetSymbolAddress((void**)&Hf, g_Hf);
    cudaGetSymbolAddress((void**)&Wf, g_Wf);
    cudaGetSymbolAddress(&zp, g_zero);

    const int SMEM = 64 * SA_STRIDE * 2 + 192 * 64 * 2;  // 26624 + 24576 = 51200
    cudaFuncSetAttribute((const void*)gemm3_kernel<true, true, true>,
                         cudaFuncAttributeMaxDynamicSharedMemorySize, SMEM);
    cudaFuncSetAttribute((const void*)gemm3_kernel<true, true, false>,
                         cudaFuncAttributeMaxDynamicSharedMemorySize, SMEM);
    cudaFuncSetAttribute((const void*)gemm3_kernel<false, false, false>,
                         cudaFuncAttributeMaxDynamicSharedMemorySize, SMEM);

    const int NB_E2 = (EE / 2 + 255) / 256;
    const int NB_P = (NN * 16 + 255) / 256;   // 16 threads per row
    const int NB_G = (NN + 63) / 64;

    cudaMemsetAsync(zp, 0, ZERO_BYTES);
    degw_kernel<<<NB_E2 + 3, 256>>>(ei, attr, W1, W2, W3);
    scan_kernel<<<NBLK, 1024>>>();
    fill_kernel<<<NB_E2, 256>>>(ei, attr);

    // Layer 1: T1 = S*x (fp32 gather), U = S*T1, H0 = relu([x|T1|U] @ Wf1 + b1)
    prop_kernel<true><<<NB_P, 256>>>(x, T1);
    prop_kernel<false><<<NB_P, 256>>>(T1, T2);
    gemm3_kernel<true, true, true><<<NB_G, 256, SMEM>>>(x, T1, T2, Wf, b1, H0);
    // Layer 2
    prop_kernel<false><<<NB_P, 256>>>(H0, T1);
    prop_kernel<false><<<NB_P, 256>>>(T1, T2);
    gemm3_kernel<true, true, false><<<NB_G, 256, SMEM>>>(H0, T1, T2, Wf + 192 * 64, b2, H1);
    // Layer 3 (fp32 output for pooling)
    prop_kernel<false><<<NB_P, 256>>>(H1, T1);
    prop_kernel<false><<<NB_P, 256>>>(T1, T2);
    gemm3_kernel<false, false, false><<<NB_G, 256, SMEM>>>(H1, T1, T2, Wf + 2 * 192 * 64, b3, Hf);

    pool_mlp_kernel<<<GG, 256>>>(Hf, bat, Wl1, bl1, Wl2, bl2, out);
}

// round 12
// speedup vs baseline: 1.3349x; 1.0477x over previous
#include <cuda_runtime.h>
#include <cuda_fp16.h>
#include <mma.h>

using namespace nvcuda;

#define NN 50000
#define EE 800000
#define F 64
#define GG 64
#define CC 10
#define NBLK 49      // ceil(NN/1024)
#define PROPBLK 740  // 148 SMs x 5 resident CTAs

typedef unsigned long long ull;

// ---------------- scratch (device globals; no allocation allowed) ----------------
#define WDEG_OFF    0
#define DEGCNT_OFF  (NN * 4)
#define STATE_OFF   (2 * NN * 4)
#define POOLCNT_OFF (STATE_OFF + 64 * 8)
#define ZERO_BYTES  (POOLCNT_OFF + 16)
__device__ __align__(16) unsigned char g_zero[ZERO_BYTES];

__device__ __align__(16) float  g_dinv[NN];
__device__ __align__(16) int    g_rowptr[NN + 1];
__device__ __align__(16) int    g_epos[EE];      // per-edge slot within its row
__device__ __align__(16) int2   g_edges[EE];     // (col, bitcast(norm)) sorted by row
__device__ __align__(16) __half g_T1[NN * F];
__device__ __align__(16) __half g_T2[NN * F];
__device__ __align__(16) __half g_H0[NN * F];
__device__ __align__(16) __half g_H1[NN * F];
__device__ __align__(16) float  g_Hf[NN * F];    // fp32 final layer output
__device__ __align__(16) float  g_pool[GG * F];
__device__ __align__(16) __half g_Wf[3 * 192 * 64];  // pre-folded fp16 weights per layer

// fp16 pack/unpack helpers (8 bytes = 4 features)
__device__ __forceinline__ float4 h4_to_f4(uint2 u) {
    float2 a = __half22float2(*reinterpret_cast<const __half2*>(&u.x));
    float2 b = __half22float2(*reinterpret_cast<const __half2*>(&u.y));
    return make_float4(a.x, a.y, b.x, b.y);
}
__device__ __forceinline__ uint2 f4_to_h4(float4 v) {
    __half2 a = __floats2half2_rn(v.x, v.y);
    __half2 b = __floats2half2_rn(v.z, v.w);
    uint2 u;
    u.x = *reinterpret_cast<unsigned*>(&a);
    u.y = *reinterpret_cast<unsigned*>(&b);
    return u;
}

// ---------------- fused build: blocks 0-2 fold W, rest do degree (2 edges/thread) ----
// Also records each edge's within-row slot (epos) so fill needs no atomics.
__global__ void degw_kernel(const int* __restrict__ ei, const float* __restrict__ attr,
                            const float* __restrict__ W1, const float* __restrict__ W2,
                            const float* __restrict__ W3) {
    if (blockIdx.x < 3) {
        int b = blockIdx.x;
        const float* W = (b == 0) ? W1 : (b == 1) ? W2 : W3;
        __half* dst = g_Wf + b * 192 * 64;
        int tid = threadIdx.x;
        for (int i = tid; i < 1024; i += 256) {
            int k = i >> 4, c = i & 15;
            float4 w0 = ((const float4*)W)[i];
            float4 w1 = ((const float4*)W)[1024 + i];
            float4 w2 = ((const float4*)W)[2048 + i];
            float4 f0 = make_float4(w0.x - w2.x, w0.y - w2.y, w0.z - w2.z, w0.w - w2.w);
            float4 f2 = make_float4(2.f * w2.x, 2.f * w2.y, 2.f * w2.z, 2.f * w2.w);
            *(uint2*)&dst[k * 64 + c * 4]         = f4_to_h4(f0);
            *(uint2*)&dst[(64 + k) * 64 + c * 4]  = f4_to_h4(w1);
            *(uint2*)&dst[(128 + k) * 64 + c * 4] = f4_to_h4(f2);
        }
        return;
    }
    float* wdeg = (float*)(g_zero + WDEG_OFF);
    int* degcnt = (int*)(g_zero + DEGCNT_OFF);
    int t = (blockIdx.x - 3) * blockDim.x + threadIdx.x;
    int e0 = t * 2;
    if (e0 + 1 < EE) {
        int2 r2 = *(const int2*)(ei + e0);
        float2 a2 = *(const float2*)(attr + e0);
        atomicAdd(&wdeg[r2.x], a2.x);
        atomicAdd(&wdeg[r2.y], a2.y);
        g_epos[e0]     = atomicAdd(&degcnt[r2.x], 1);
        g_epos[e0 + 1] = atomicAdd(&degcnt[r2.y], 1);
    } else if (e0 < EE) {
        int r = ei[e0];
        atomicAdd(&wdeg[r], attr[e0]);
        g_epos[e0] = atomicAdd(&degcnt[r], 1);
    }
}

// Single-kernel scan + dinv + rowptr init. 49 blocks x 1024 (one wave).
__global__ void scan_kernel() {
    float* wdeg = (float*)(g_zero + WDEG_OFF);
    int* degcnt = (int*)(g_zero + DEGCNT_OFF);
    volatile ull* state = (volatile ull*)(g_zero + STATE_OFF);

    int tid = threadIdx.x;
    int b = blockIdx.x;
    int i = b * 1024 + tid;
    int v = (i < NN) ? degcnt[i] : 0;

    if (i < NN) {
        float d = wdeg[i];
        g_dinv[i] = (d > 0.f) ? rsqrtf(d) : 0.f;
    }

    int lane = tid & 31, wid = tid >> 5;
    int x = v;
    #pragma unroll
    for (int o = 1; o < 32; o <<= 1) {
        int y = __shfl_up_sync(0xFFFFFFFFu, x, o);
        if (lane >= o) x += y;
    }
    __shared__ int ws[32];
    __shared__ int s_prefix;
    if (lane == 31) ws[wid] = x;
    __syncthreads();
    if (wid == 0) {
        int s = ws[lane];
        #pragma unroll
        for (int o = 1; o < 32; o <<= 1) {
            int y = __shfl_up_sync(0xFFFFFFFFu, s, o);
            if (lane >= o) s += y;
        }
        ws[lane] = s;
    }
    __syncthreads();
    int blocksum = ws[31];

    if (tid == 0) {
        atomicExch((ull*)&state[b], (1ull << 32) | (unsigned)blocksum);
    }
    if (tid < 32) {
        int acc = 0;
        for (int p = tid; p < b; p += 32) {
            ull sv;
            do { sv = state[p]; } while ((sv >> 32) == 0);
            acc += (int)(unsigned)sv;
        }
        #pragma unroll
        for (int o = 16; o > 0; o >>= 1) acc += __shfl_down_sync(0xFFFFFFFFu, acc, o);
        if (tid == 0) s_prefix = acc;
    }
    __syncthreads();

    int excl = x - v + (wid > 0 ? ws[wid - 1] : 0);
    if (i < NN) {
        g_rowptr[i] = excl + s_prefix;
    }
    if (b == 0 && tid == 0) g_rowptr[NN] = EE;
}

// Atomic-free fill: slot precomputed in degw (epos), pure scatter stores.
__global__ void fill_kernel(const int* __restrict__ ei, const float* __restrict__ attr) {
    int t = blockIdx.x * blockDim.x + threadIdx.x;
    int e0 = t * 2;
    if (e0 + 1 < EE) {
        int2 r2 = *(const int2*)(ei + e0);
        int2 c2 = *(const int2*)(ei + EE + e0);
        float2 a2 = *(const float2*)(attr + e0);
        int2 p2 = *(const int2*)(g_epos + e0);
        float w0 = -a2.x * g_dinv[r2.x] * g_dinv[c2.x];
        float w1 = -a2.y * g_dinv[r2.y] * g_dinv[c2.y];
        g_edges[g_rowptr[r2.x] + p2.x] = make_int2(c2.x, __float_as_int(w0));
        g_edges[g_rowptr[r2.y] + p2.y] = make_int2(c2.y, __float_as_int(w1));
    } else if (e0 < EE) {
        int r = ei[e0];
        int c = ei[EE + e0];
        float w = -attr[e0] * g_dinv[r] * g_dinv[c];
        g_edges[g_rowptr[r] + g_epos[e0]] = make_int2(c, __float_as_int(w));
    }
}

// ---------------- sparse propagation: persistent, half-warp (16 lanes) per row -------
// F32IN: gather fp32 rows (layer-1 input x). Else fp16. Output fp16. fp32 accumulate.
// Grid-stride over rows: 740 resident CTAs, no CTA churn.
template <bool F32IN>
__global__ __launch_bounds__(256, 5) void prop_kernel(const void* __restrict__ in_,
                                                      uint2* __restrict__ out) {
    const uint2* inh = (const uint2*)in_;
    const float4* inf = (const float4*)in_;
    int l = threadIdx.x & 15;
    int hw0 = (blockIdx.x * blockDim.x + threadIdx.x) >> 4;
    const int nhw = (PROPBLK * 256) >> 4;  // 11840 half-warps

    for (int row = hw0; row < NN; row += nhw) {
        int s = g_rowptr[row], e = g_rowptr[row + 1];

        float4 A = make_float4(0.f, 0.f, 0.f, 0.f);
        float4 B = make_float4(0.f, 0.f, 0.f, 0.f);
        int j = s;
        for (; j + 4 <= e; j += 4) {
            int2 e0 = g_edges[j];
            int2 e1 = g_edges[j + 1];
            int2 e2 = g_edges[j + 2];
            int2 e3 = g_edges[j + 3];
            float4 v0, v1, v2, v3;
            if (F32IN) {
                v0 = inf[e0.x * 16 + l];
                v1 = inf[e1.x * 16 + l];
                v2 = inf[e2.x * 16 + l];
                v3 = inf[e3.x * 16 + l];
            } else {
                uint2 u0 = inh[e0.x * 16 + l];
                uint2 u1 = inh[e1.x * 16 + l];
                uint2 u2 = inh[e2.x * 16 + l];
                uint2 u3 = inh[e3.x * 16 + l];
                v0 = h4_to_f4(u0);
                v1 = h4_to_f4(u1);
                v2 = h4_to_f4(u2);
                v3 = h4_to_f4(u3);
            }
            float w0 = __int_as_float(e0.y);
            float w1 = __int_as_float(e1.y);
            float w2 = __int_as_float(e2.y);
            float w3 = __int_as_float(e3.y);
            A.x = fmaf(w0, v0.x, A.x); A.y = fmaf(w0, v0.y, A.y);
            A.z = fmaf(w0, v0.z, A.z); A.w = fmaf(w0, v0.w, A.w);
            B.x = fmaf(w1, v1.x, B.x); B.y = fmaf(w1, v1.y, B.y);
            B.z = fmaf(w1, v1.z, B.z); B.w = fmaf(w1, v1.w, B.w);
            A.x = fmaf(w2, v2.x, A.x); A.y = fmaf(w2, v2.y, A.y);
            A.z = fmaf(w2, v2.z, A.z); A.w = fmaf(w2, v2.w, A.w);
            B.x = fmaf(w3, v3.x, B.x); B.y = fmaf(w3, v3.y, B.y);
            B.z = fmaf(w3, v3.z, B.z); B.w = fmaf(w3, v3.w, B.w);
        }
        for (; j < e; j++) {
            int2 ed = g_edges[j];
            float4 v;
            if (F32IN) {
                v = inf[ed.x * 16 + l];
            } else {
                v = h4_to_f4(inh[ed.x * 16 + l]);
            }
            float w = __int_as_float(ed.y);
            A.x = fmaf(w, v.x, A.x); A.y = fmaf(w, v.y, A.y);
            A.z = fmaf(w, v.z, A.z); A.w = fmaf(w, v.w, A.w);
        }
        float4 r = make_float4(A.x + B.x, A.y + B.y, A.z + B.z, A.w + B.w);
        out[row * 16 + l] = f4_to_h4(r);
    }
}

// ---------------- tensor-core GEMM: out = relu?([x|T1|U] @ Wf + b) ----------------
// A: 64x192 fp16 (x0 may be fp32 source, converted in staging), B: pre-folded 192x64 fp16.
#define SA_STRIDE 208   // 192 + 16 padding
template <bool RELU, bool OUTH, bool X0F32>
__global__ __launch_bounds__(256, 2) void gemm3_kernel(
    const void* __restrict__ x0, const uint2* __restrict__ x1, const uint2* __restrict__ x2,
    const __half* __restrict__ Wf, const float* __restrict__ b, void* __restrict__ out) {
    extern __shared__ char smem[];
    __half* sA = (__half*)smem;                          // 64 x SA_STRIDE fp16 = 26624 B
    __half* sB = (__half*)(smem + 64 * SA_STRIDE * 2);   // 192 x 64 fp16 = 24576 B
    float*  sC = (float*)smem;                           // reused after MMA: 64x64 fp32

    int tid = threadIdx.x;
    int row0 = blockIdx.x * 64;

    // stage A slot 0 (x)
    for (int i = tid; i < 1024; i += 256) {
        int r = i >> 4, c = i & 15;
        int row = row0 + r;
        uint2 v;
        if (X0F32) {
            float4 f = (row < NN) ? ((const float4*)x0)[row * 16 + c]
                                  : make_float4(0.f, 0.f, 0.f, 0.f);
            v = f4_to_h4(f);
        } else {
            v = (row < NN) ? ((const uint2*)x0)[row * 16 + c] : make_uint2(0u, 0u);
        }
        *(uint2*)&sA[r * SA_STRIDE + c * 4] = v;
    }
    // stage A slots 1,2 (T1, U) fp16 passthrough
    #pragma unroll
    for (int m = 1; m < 3; m++) {
        const uint2* src = (m == 1) ? x1 : x2;
        for (int i = tid; i < 1024; i += 256) {
            int r = i >> 4, c = i & 15;
            int row = row0 + r;
            uint2 v = (row < NN) ? src[row * 16 + c] : make_uint2(0u, 0u);
            *(uint2*)&sA[r * SA_STRIDE + m * 64 + c * 4] = v;
        }
    }
    // stage B: straight copy of pre-folded fp16 weights (24576 B = 1536 uint4)
    {
        uint4* d = (uint4*)sB;
        const uint4* g = (const uint4*)Wf;
        #pragma unroll
        for (int i = tid; i < 1536; i += 256) d[i] = g[i];
    }
    __syncthreads();

    // MMA: warp w -> tiles (wm, wn) and (wm+2, wn)
    int w = tid >> 5;
    int wm = w >> 2;   // 0..1
    int wn = w & 3;    // 0..3
    wmma::fragment<wmma::accumulator, 16, 16, 16, float> acc0, acc1;
    wmma::fill_fragment(acc0, 0.f);
    wmma::fill_fragment(acc1, 0.f);
    #pragma unroll
    for (int k = 0; k < 192; k += 16) {
        wmma::fragment<wmma::matrix_a, 16, 16, 16, __half, wmma::row_major> a0, a1;
        wmma::fragment<wmma::matrix_b, 16, 16, 16, __half, wmma::row_major> bf;
        wmma::load_matrix_sync(a0, sA + (wm * 16) * SA_STRIDE + k, SA_STRIDE);
        wmma::load_matrix_sync(a1, sA + (wm * 16 + 32) * SA_STRIDE + k, SA_STRIDE);
        wmma::load_matrix_sync(bf, sB + k * 64 + wn * 16, 64);
        wmma::mma_sync(acc0, a0, bf, acc0);
        wmma::mma_sync(acc1, a1, bf, acc1);
    }
    __syncthreads();  // done reading sA; reuse as sC
    wmma::store_matrix_sync(sC + (wm * 16) * 64 + wn * 16, acc0, 64, wmma::mem_row_major);
    wmma::store_matrix_sync(sC + (wm * 16 + 32) * 64 + wn * 16, acc1, 64, wmma::mem_row_major);
    __syncthreads();

    // epilogue: bias + relu + store
    for (int i = tid; i < 1024; i += 256) {
        int r = i >> 4, c = i & 15;
        int row = row0 + r;
        if (row < NN) {
            float4 v = ((const float4*)sC)[i];
            float4 bias = ((const float4*)b)[c];
            v.x += bias.x; v.y += bias.y; v.z += bias.z; v.w += bias.w;
            if (RELU) {
                v.x = fmaxf(v.x, 0.f); v.y = fmaxf(v.y, 0.f);
                v.z = fmaxf(v.z, 0.f); v.w = fmaxf(v.w, 0.f);
            }
            if (OUTH) {
                ((uint2*)out)[row * 16 + c] = f4_to_h4(v);
            } else {
                ((float4*)out)[row * 16 + c] = v;
            }
        }
    }
}

// ---------------- mean pool per graph + last-block MLP ----------------
__device__ __forceinline__ int lower_bound_batch(const int* b, int val) {
    int lo = 0, hi = NN;
    while (lo < hi) {
        int mid = (lo + hi) >> 1;
        if (b[mid] < val) lo = mid + 1; else hi = mid;
    }
    return lo;
}

__global__ void pool_mlp_kernel(const float* __restrict__ h, const int* __restrict__ batch,
                                const float* __restrict__ Wl1, const float* __restrict__ bl1,
                                const float* __restrict__ Wl2, const float* __restrict__ bl2,
                                float* __restrict__ out) {
    int g = blockIdx.x;
    __shared__ int s_lo, s_hi;
    if (threadIdx.x == 0) {
        s_lo = lower_bound_batch(batch, g);
        s_hi = lower_bound_batch(batch, g + 1);
    }
    __syncthreads();
    int lo = s_lo, hi = s_hi;
    int f = threadIdx.x & 63;
    int part = threadIdx.x >> 6;
    float acc = 0.f;
    for (int i = lo + part; i < hi; i += 4) acc += h[i * 64 + f];
    __shared__ float sh[4][64];
    sh[part][f] = acc;
    __syncthreads();
    if (part == 0) {
        float s = sh[0][f] + sh[1][f] + sh[2][f] + sh[3][f];
        float cnt = (float)(hi - lo);
        g_pool[g * 64 + f] = s / fmaxf(cnt, 1.f);
    }
    // last-block pattern: final pool block runs the MLP
    __threadfence();
    __shared__ int s_last;
    __syncthreads();
    if (threadIdx.x == 0) {
        int* cnt = (int*)(g_zero + POOLCNT_OFF);
        s_last = (atomicAdd(cnt, 1) == GG - 1);
    }
    __syncthreads();
    if (!s_last) return;
    __threadfence();  // acquire: all g_pool writes visible

    __shared__ float sp[GG * 64];
    __shared__ float sh1[GG * 32];
    int tid = threadIdx.x;
    for (int i = tid; i < GG * 64; i += 256) sp[i] = g_pool[i];
    __syncthreads();
    for (int i = tid; i < GG * 32; i += 256) {
        int gg = i >> 5, c = i & 31;
        float s = bl1[c];
        #pragma unroll 8
        for (int k = 0; k < 64; k++) s += sp[gg * 64 + k] * Wl1[k * 32 + c];
        sh1[i] = fmaxf(s, 0.f);
    }
    __syncthreads();
    for (int i = tid; i < GG * CC; i += 256) {
        int gg = i / CC, c = i % CC;
        float s = bl2[c];
        #pragma unroll
        for (int k = 0; k < 32; k++) s += sh1[gg * 32 + k] * Wl2[k * CC + c];
        out[i] = s;
    }
}

// ---------------- launcher ----------------
extern "C" void kernel_launch(void* const* d_in, const int* in_sizes, int n_in,
                              void* d_out, int out_size) {
    const float* x    = (const float*)d_in[0];
    const int*   ei   = (const int*)d_in[1];
    const float* attr = (const float*)d_in[2];
    const int*   bat  = (const int*)d_in[3];
    const float* W1 = (const float*)d_in[4];
    const float* b1 = (const float*)d_in[5];
    const float* W2 = (const float*)d_in[6];
    const float* b2 = (const float*)d_in[7];
    const float* W3 = (const float*)d_in[8];
    const float* b3 = (const float*)d_in[9];
    const float* Wl1 = (const float*)d_in[10];
    const float* bl1 = (const float*)d_in[11];
    const float* Wl2 = (const float*)d_in[12];
    const float* bl2 = (const float*)d_in[13];
    float* out = (float*)d_out;

    uint2 *T1, *T2, *H0, *H1;
    __half* Wf;
    float *Hf;
    void* zp;
    cudaGetSymbolAddress((void**)&T1, g_T1);
    cudaGetSymbolAddress((void**)&T2, g_T2);
    cudaGetSymbolAddress((void**)&H0, g_H0);
    cudaGetSymbolAddress((void**)&H1, g_H1);
    cudaGetSymbolAddress((void**)&Hf, g_Hf);
    cudaGetSymbolAddress((void**)&Wf, g_Wf);
    cudaGetSymbolAddress(&zp, g_zero);

    const int SMEM = 64 * SA_STRIDE * 2 + 192 * 64 * 2;  // 26624 + 24576 = 51200
    cudaFuncSetAttribute((const void*)gemm3_kernel<true, true, true>,
                         cudaFuncAttributeMaxDynamicSharedMemorySize, SMEM);
    cudaFuncSetAttribute((const void*)gemm3_kernel<true, true, false>,
                         cudaFuncAttributeMaxDynamicSharedMemorySize, SMEM);
    cudaFuncSetAttribute((const void*)gemm3_kernel<false, false, false>,
                         cudaFuncAttributeMaxDynamicSharedMemorySize, SMEM);

    const int NB_E2 = (EE / 2 + 255) / 256;
    const int NB_G = (NN + 63) / 64;

    cudaMemsetAsync(zp, 0, ZERO_BYTES);
    degw_kernel<<<NB_E2 + 3, 256>>>(ei, attr, W1, W2, W3);
    scan_kernel<<<NBLK, 1024>>>();
    fill_kernel<<<NB_E2, 256>>>(ei, attr);

    // Layer 1: T1 = S*x (fp32 gather), U = S*T1, H0 = relu([x|T1|U] @ Wf1 + b1)
    prop_kernel<true><<<PROPBLK, 256>>>(x, T1);
    prop_kernel<false><<<PROPBLK, 256>>>(T1, T2);
    gemm3_kernel<true, true, true><<<NB_G, 256, SMEM>>>(x, T1, T2, Wf, b1, H0);
    // Layer 2
    prop_kernel<false><<<PROPBLK, 256>>>(H0, T1);
    prop_kernel<false><<<PROPBLK, 256>>>(T1, T2);
    gemm3_kernel<true, true, false><<<NB_G, 256, SMEM>>>(H0, T1, T2, Wf + 192 * 64, b2, H1);
    // Layer 3 (fp32 output for pooling)
    prop_kernel<false><<<PROPBLK, 256>>>(H1, T1);
    prop_kernel<false><<<PROPBLK, 256>>>(T1, T2);
    gemm3_kernel<false, false, false><<<NB_G, 256, SMEM>>>(H1, T1, T2, Wf + 2 * 192 * 64, b3, Hf);

    pool_mlp_kernel<<<GG, 256>>>(Hf, bat, Wl1, bl1, Wl2, bl2, out);
}